// round 13
// baseline (speedup 1.0000x reference)
#include <cuda_runtime.h>
#include <cuda_fp16.h>
#include <mma.h>

using namespace nvcuda;

#define Nn 50000
#define Ee 1600000
#define FIN 256
#define HD 128
#define NEG 0.2f
#define EPSf 1e-9f

// ---------------- scratch (static device globals) ----------------------------
__device__ float  g_hsrc[Nn * HD];        // fp32 h_src
__device__ float  g_hdst[Nn * HD];        // residual branch (bias added at end)
__device__ __half g_feat16[Nn * FIN];     // fp16 feat for TC GEMM
__device__ __half g_w16[2][FIN * HD];     // fp16 W_src / W_dst
__device__ __half g_h16[3][Nn * HD];      // fp16 gather sources
__device__ __half g_hs16[3][Nn * HD];     // fp16 transformed hops: [0]=hs1,[1]=hs2,[2]=h0
__device__ float  g_asrc[Nn * 2];
__device__ float  g_adst[Nn * 2];
__device__ float  g_acsr[Ee * 2];         // CSR: exp(logit)
__device__ unsigned g_aw16[Ee];           // CSR: normalized weights, half2 (h0,h1)
__device__ int    g_srcc[Ee];
__device__ int    g_cnt[Nn];
__device__ int    g_rp[Nn + 1];
__device__ int    g_cur[Nn];
__device__ float  g_sums[Nn * 2];         // src-direction softmax denominators

__device__ __forceinline__ float leaky(float x) { return x > 0.f ? x : NEG * x; }

// ---------------- W fp32 -> fp16 (tiny) --------------------------------------
__global__ void wconv_kernel(const float* __restrict__ Wsrc,
                             const float* __restrict__ Wdst)
{
    int i = blockIdx.x * blockDim.x + threadIdx.x;
    if (i < FIN * HD / 2) {
        float2 a = ((const float2*)Wsrc)[i];
        float2 b = ((const float2*)Wdst)[i];
        *(__half2*)&g_w16[0][i * 2] = __floats2half2_rn(a.x, a.y);
        *(__half2*)&g_w16[1][i * 2] = __floats2half2_rn(b.x, b.y);
    }
}

// ---------------- fused: feat fp32->fp16 + attention projections -------------
__global__ void convert_attn_kernel(const float* __restrict__ feat,
                                    const float* __restrict__ Wasrc,
                                    const float* __restrict__ Wadst)
{
    int gw = (blockIdx.x * blockDim.x + threadIdx.x) >> 5;
    int lane = threadIdx.x & 31;
    if (gw >= Nn) return;
    const float4* frow = (const float4*)&feat[gw * FIN];
    float4 x0 = frow[lane];
    float4 x1 = frow[lane + 32];
    uint2 r0, r1;
    *(__half2*)&r0.x = __floats2half2_rn(x0.x, x0.y);
    *(__half2*)&r0.y = __floats2half2_rn(x0.z, x0.w);
    *(__half2*)&r1.x = __floats2half2_rn(x1.x, x1.y);
    *(__half2*)&r1.y = __floats2half2_rn(x1.z, x1.w);
    ((uint2*)g_feat16)[gw * 64 + lane] = r0;
    ((uint2*)g_feat16)[gw * 64 + 32 + lane] = r1;

    int c0 = lane * 4, c1 = 128 + lane * 4;
    float s0 = 0.f, s1 = 0.f, d0 = 0.f, d1 = 0.f;
    #pragma unroll
    for (int j = 0; j < 4; j++) {
        float xa = (&x0.x)[j];
        float2 ws = ((const float2*)Wasrc)[c0 + j];
        float2 wd = ((const float2*)Wadst)[c0 + j];
        s0 += xa * ws.x; s1 += xa * ws.y;
        d0 += xa * wd.x; d1 += xa * wd.y;
        float xb = (&x1.x)[j];
        float2 ws1 = ((const float2*)Wasrc)[c1 + j];
        float2 wd1 = ((const float2*)Wadst)[c1 + j];
        s0 += xb * ws1.x; s1 += xb * ws1.y;
        d0 += xb * wd1.x; d1 += xb * wd1.y;
    }
    #pragma unroll
    for (int o = 16; o; o >>= 1) {
        s0 += __shfl_xor_sync(0xffffffffu, s0, o);
        s1 += __shfl_xor_sync(0xffffffffu, s1, o);
        d0 += __shfl_xor_sync(0xffffffffu, d0, o);
        d1 += __shfl_xor_sync(0xffffffffu, d1, o);
    }
    if (lane == 0) {
        ((float2*)g_asrc)[gw] = make_float2(s0, s1);
        ((float2*)g_adst)[gw] = make_float2(d0, d1);
    }
}

// ---------------- tensor-core GEMM: Out = feat16 @ W16 -----------------------
__global__ __launch_bounds__(256) void gemm_tc_kernel()
{
    __shared__ __half Bs[FIN * 64];
    int wsel = blockIdx.y & 1;
    int nhalf = blockIdx.y >> 1;
    const uint2* wsrc = (const uint2*)g_w16[wsel];
    uint2* bs = (uint2*)Bs;
    for (int i = threadIdx.x; i < FIN * 16; i += 256) {
        int r = i >> 4, c = i & 15;
        bs[r * 16 + c] = wsrc[r * 32 + nhalf * 16 + c];
    }
    __syncthreads();
    int wid = threadIdx.x >> 5;
    int row0 = blockIdx.x * 128 + wid * 16;
    if (row0 >= Nn) return;

    wmma::fragment<wmma::accumulator, 16, 16, 16, float> acc[4];
    #pragma unroll
    for (int n = 0; n < 4; n++) wmma::fill_fragment(acc[n], 0.f);
    const __half* arow = g_feat16 + row0 * FIN;
    #pragma unroll 4
    for (int kt = 0; kt < 16; kt++) {
        wmma::fragment<wmma::matrix_a, 16, 16, 16, __half, wmma::row_major> af;
        wmma::load_matrix_sync(af, arow + kt * 16, FIN);
        #pragma unroll
        for (int n = 0; n < 4; n++) {
            wmma::fragment<wmma::matrix_b, 16, 16, 16, __half, wmma::row_major> bf;
            wmma::load_matrix_sync(bf, Bs + kt * 16 * 64 + n * 16, 64);
            wmma::mma_sync(acc[n], af, bf, acc[n]);
        }
    }
    float* Out = wsel ? g_hdst : g_hsrc;
    #pragma unroll
    for (int n = 0; n < 4; n++)
        wmma::store_matrix_sync(Out + row0 * HD + nhalf * 64 + n * 16,
                                acc[n], HD, wmma::mem_row_major);
}

// ---------------- CSR build --------------------------------------------------
__global__ void hist_kernel(const int* __restrict__ dst) {
    int i = blockIdx.x * blockDim.x + threadIdx.x;   // 4 edges per thread
    int e0 = i * 4;
    if (e0 + 3 < Ee) {
        int4 d = ((const int4*)dst)[i];
        atomicAdd(&g_cnt[d.x], 1);
        atomicAdd(&g_cnt[d.y], 1);
        atomicAdd(&g_cnt[d.z], 1);
        atomicAdd(&g_cnt[d.w], 1);
    } else {
        for (int e = e0; e < Ee; e++) atomicAdd(&g_cnt[dst[e]], 1);
    }
}

// scan also re-zeroes cnt and sums for the NEXT call (deterministic per call:
// hist/place within the same call see zeros established by the previous call's
// scan, or static zero-init on the very first call).
__global__ __launch_bounds__(1024) void scan_kernel() {
    __shared__ int part[1024];
    const int CH = (Nn + 1023) / 1024;
    int t = threadIdx.x;
    int start = t * CH;
    int s = 0;
    for (int i = 0; i < CH; i++) {
        int idx = start + i;
        if (idx < Nn) s += g_cnt[idx];
    }
    part[t] = s;
    __syncthreads();
    for (int off = 1; off < 1024; off <<= 1) {
        int v = (t >= off) ? part[t - off] : 0;
        __syncthreads();
        part[t] += v;
        __syncthreads();
    }
    int base = (t == 0) ? 0 : part[t - 1];
    for (int i = 0; i < CH; i++) {
        int idx = start + i;
        if (idx < Nn) {
            int c = g_cnt[idx];
            g_rp[idx] = base;
            g_cur[idx] = base;
            base += c;
            g_cnt[idx] = 0;
            ((float2*)g_sums)[idx] = make_float2(0.f, 0.f);
        }
    }
    if (t == 1023) g_rp[Nn] = Ee;
}

// ---------------- place + edge logits/exp + src-sum atomics ------------------
__global__ void place_edge_kernel(const int* __restrict__ src, const int* __restrict__ dst) {
    int e = blockIdx.x * blockDim.x + threadIdx.x;
    if (e >= Ee) return;
    int s = src[e], d = dst[e];
    int pos = atomicAdd(&g_cur[d], 1);
    g_srcc[pos] = s;
    float2 as = ((const float2*)g_asrc)[s];
    float2 ad = ((const float2*)g_adst)[d];
    float e0 = __expf(leaky(as.x + ad.x));
    float e1 = __expf(leaky(as.y + ad.y));
    ((float2*)g_acsr)[pos] = make_float2(e0, e1);
    atomicAdd(&g_sums[s * 2], e0);     atomicAdd(&g_sums[s * 2 + 1], e1);
}

// ---------------- feat_trans helpers -----------------------------------------
// 4-float/lane variant (ft0: full-warp, 16-lane head groups)
__device__ __forceinline__ float4 feat_trans4(
    float4 acc, int lane, int k,
    const float* __restrict__ scale, const float* __restrict__ offset,
    const float* __restrict__ pemb)
{
    float s = acc.x + acc.y + acc.z + acc.w;
    float sq = acc.x * acc.x + acc.y * acc.y + acc.z * acc.z + acc.w * acc.w;
    #pragma unroll
    for (int o = 8; o; o >>= 1) {
        s  += __shfl_xor_sync(0xffffffffu, s,  o, 16);
        sq += __shfl_xor_sync(0xffffffffu, sq, o, 16);
    }
    float mean = s * (1.f / 64.f);
    float var = sq * (1.f / 64.f) - mean * mean + EPSf;
    float rs = rsqrtf(var);
    float4 sc = ((const float4*)scale)[k * 32 + lane];
    float4 of = ((const float4*)offset)[k * 32 + lane];
    float4 pe = ((const float4*)pemb)[k * 32 + lane];
    float4 y;
    y.x = (acc.x - mean) * sc.x * rs + of.x + pe.x;
    y.y = (acc.y - mean) * sc.y * rs + of.y + pe.y;
    y.z = (acc.z - mean) * sc.z * rs + of.z + pe.z;
    y.w = (acc.w - mean) * sc.w * rs + of.w + pe.w;
    return y;
}

// 8-float/lane variant: lane lo (=lane&15) covers cols [lo*8, lo*8+8);
// head groups are 8-lane (lo 0-7 = head0, 8-15 = head1).
__device__ __forceinline__ void feat_trans8(
    float acc[8], int lo, int k,
    const float* __restrict__ scale, const float* __restrict__ offset,
    const float* __restrict__ pemb, float out[8])
{
    float s = 0.f, sq = 0.f;
    #pragma unroll
    for (int i = 0; i < 8; i++) { s += acc[i]; sq += acc[i] * acc[i]; }
    #pragma unroll
    for (int o = 4; o; o >>= 1) {
        s  += __shfl_xor_sync(0xffffffffu, s,  o, 8);
        sq += __shfl_xor_sync(0xffffffffu, sq, o, 8);
    }
    float mean = s * (1.f / 64.f);
    float var = sq * (1.f / 64.f) - mean * mean + EPSf;
    float rs = rsqrtf(var);
    const float4* sc4 = (const float4*)&scale[k * HD + lo * 8];
    const float4* of4 = (const float4*)&offset[k * HD + lo * 8];
    const float4* pe4 = (const float4*)&pemb[k * HD + lo * 8];
    float4 sa = sc4[0], sb = sc4[1];
    float4 oa = of4[0], ob = of4[1];
    float4 pa = pe4[0], pb = pe4[1];
    const float* scp = &sa.x; const float* ofp = &oa.x; const float* pep = &pa.x;
    #pragma unroll
    for (int i = 0; i < 4; i++)
        out[i] = (acc[i] - mean) * scp[i] * rs + ofp[i] + pep[i];
    scp = &sb.x; ofp = &ob.x; pep = &pb.x;
    #pragma unroll
    for (int i = 0; i < 4; i++)
        out[4 + i] = (acc[4 + i] - mean) * scp[i] * rs + ofp[i] + pep[i];
}

__device__ __forceinline__ void store_half4(__half* __restrict__ out16,
                                            int idx4, float4 v)
{
    uint2 raw;
    *(__half2*)&raw.x = __floats2half2_rn(v.x, v.y);
    *(__half2*)&raw.y = __floats2half2_rn(v.z, v.w);
    ((uint2*)out16)[idx4] = raw;
}

// pack/store 8 floats as uint4 of halves at [node*16 + lo]
__device__ __forceinline__ void store_half8(__half* __restrict__ out16,
                                            int idx16, const float* v)
{
    uint4 raw;
    *(__half2*)&raw.x = __floats2half2_rn(v[0], v[1]);
    *(__half2*)&raw.y = __floats2half2_rn(v[2], v[3]);
    *(__half2*)&raw.z = __floats2half2_rn(v[4], v[5]);
    *(__half2*)&raw.w = __floats2half2_rn(v[6], v[7]);
    ((uint4*)out16)[idx16] = raw;
}

__device__ __forceinline__ void load_half8(const __half* __restrict__ in16,
                                           int idx16, float* v)
{
    uint4 raw = ((const uint4*)in16)[idx16];
    float2 f0 = __half22float2(*(const __half2*)&raw.x);
    float2 f1 = __half22float2(*(const __half2*)&raw.y);
    float2 f2 = __half22float2(*(const __half2*)&raw.z);
    float2 f3 = __half22float2(*(const __half2*)&raw.w);
    v[0] = f0.x; v[1] = f0.y; v[2] = f1.x; v[3] = f1.y;
    v[4] = f2.x; v[5] = f2.y; v[6] = f3.x; v[7] = f3.y;
}

// ---------------- ft0: feat_trans(h_src,0) -> h0 (fp16), + fp16 h_src --------
__global__ void ft0_kernel(const float* __restrict__ scale,
                           const float* __restrict__ offset,
                           const float* __restrict__ pemb)
{
    int gw = (blockIdx.x * blockDim.x + threadIdx.x) >> 5;
    int lane = threadIdx.x & 31;
    if (gw >= Nn) return;
    float4 x = ((const float4*)g_hsrc)[gw * 32 + lane];
    store_half4(g_h16[0], gw * 32 + lane, x);
    store_half4(g_hs16[2], gw * 32 + lane,
                feat_trans4(x, lane, 0, scale, offset, pemb));
}

// ---------------- 2-edge-per-iteration gather core ---------------------------
// lane h = lane>>4 picks even/odd edge of the pair; lo = lane&15 covers uint4
// (8 halves) of the row. Weight = half2 (head0, head1); head by (lo>=8).
__device__ __forceinline__ void gather2_chunk(
    const uint4* __restrict__ in4, int cnt, int h, int lo, bool head1,
    int sj, unsigned wjp, float acc[8])
{
    if (cnt >= 32) {
        #pragma unroll 4
        for (int j = 0; j < 32; j += 2) {
            int s = __shfl_sync(0xffffffffu, sj, j + h);
            unsigned wp = __shfl_sync(0xffffffffu, wjp, j + h);
            __half2 w2 = *(__half2*)&wp;
            float a = __half2float(head1 ? __high2half(w2) : __low2half(w2));
            uint4 raw = in4[s * 16 + lo];
            float2 f0 = __half22float2(*(const __half2*)&raw.x);
            float2 f1 = __half22float2(*(const __half2*)&raw.y);
            float2 f2 = __half22float2(*(const __half2*)&raw.z);
            float2 f3 = __half22float2(*(const __half2*)&raw.w);
            acc[0] += a * f0.x; acc[1] += a * f0.y;
            acc[2] += a * f1.x; acc[3] += a * f1.y;
            acc[4] += a * f2.x; acc[5] += a * f2.y;
            acc[6] += a * f3.x; acc[7] += a * f3.y;
        }
    } else {
        for (int j = 0; j < cnt; j += 2) {
            int jj = j + h;
            int sel = jj < cnt ? jj : cnt - 1;
            int s = __shfl_sync(0xffffffffu, sj, sel);
            unsigned wp = __shfl_sync(0xffffffffu, wjp, sel);
            __half2 w2 = *(__half2*)&wp;
            float a = __half2float(head1 ? __high2half(w2) : __low2half(w2));
            if (jj >= cnt) a = 0.f;
            uint4 raw = in4[s * 16 + lo];
            float2 f0 = __half22float2(*(const __half2*)&raw.x);
            float2 f1 = __half22float2(*(const __half2*)&raw.y);
            float2 f2 = __half22float2(*(const __half2*)&raw.z);
            float2 f3 = __half22float2(*(const __half2*)&raw.w);
            acc[0] += a * f0.x; acc[1] += a * f0.y;
            acc[2] += a * f1.x; acc[3] += a * f1.y;
            acc[4] += a * f2.x; acc[5] += a * f2.y;
            acc[6] += a * f3.x; acc[7] += a * f3.y;
        }
    }
}

// combine half-warp partials (even/odd edge subsets of the same node)
__device__ __forceinline__ void combine16(float acc[8]) {
    #pragma unroll
    for (int i = 0; i < 8; i++)
        acc[i] += __shfl_xor_sync(0xffffffffu, acc[i], 16);
}

// ---------------- hop 1: in-warp dst-sum + normalize->aw16 + gather ----------
__global__ __launch_bounds__(256) void hop1_kernel(
    const float* __restrict__ scale, const float* __restrict__ offset,
    const float* __restrict__ pemb)
{
    int gw = (blockIdx.x * blockDim.x + threadIdx.x) >> 5;
    int lane = threadIdx.x & 31;
    if (gw >= Nn) return;
    int h = lane >> 4, lo = lane & 15;
    bool head1 = (lo >= 8);
    int b = g_rp[gw], e = g_rp[gw + 1];

    // dst-direction denominator
    float2 sd = make_float2(0.f, 0.f);
    for (int pos = b + lane; pos < e; pos += 32) {
        float2 ex = ((const float2*)g_acsr)[pos];
        sd.x += ex.x; sd.y += ex.y;
    }
    #pragma unroll
    for (int o = 16; o; o >>= 1) {
        sd.x += __shfl_xor_sync(0xffffffffu, sd.x, o);
        sd.y += __shfl_xor_sync(0xffffffffu, sd.y, o);
    }

    const uint4* in4 = (const uint4*)g_h16[0];
    float acc[8] = {};
    for (int base = b; base < e; base += 32) {
        int cnt = e - base;
        int sj = 0;
        unsigned wjp = 0;
        if (base + lane < e) {
            sj = g_srcc[base + lane];
            float2 ex = ((const float2*)g_acsr)[base + lane];
            float2 ss = ((const float2*)g_sums)[sj];
            float w0 = sqrtf(fmaxf(ex.x / sd.x, EPSf) * fmaxf(ex.x / ss.x, EPSf));
            float w1 = sqrtf(fmaxf(ex.y / sd.y, EPSf) * fmaxf(ex.y / ss.y, EPSf));
            __half2 wh = __floats2half2_rn(w0, w1);
            wjp = *(unsigned*)&wh;
            g_aw16[base + lane] = wjp;
        }
        gather2_chunk(in4, cnt, h, lo, head1, sj, wjp, acc);
    }
    combine16(acc);
    float ts[8];
    feat_trans8(acc, lo, 1, scale, offset, pemb, ts);
    if (lane < 16) {
        store_half8(g_h16[1], gw * 16 + lo, acc);
        store_half8(g_hs16[0], gw * 16 + lo, ts);
    }
}

// ---------------- hop 2: gather + feat_trans ---------------------------------
__global__ __launch_bounds__(256) void hop2_kernel(
    const float* __restrict__ scale, const float* __restrict__ offset,
    const float* __restrict__ pemb)
{
    int gw = (blockIdx.x * blockDim.x + threadIdx.x) >> 5;
    int lane = threadIdx.x & 31;
    if (gw >= Nn) return;
    int h = lane >> 4, lo = lane & 15;
    bool head1 = (lo >= 8);
    int b = g_rp[gw], e = g_rp[gw + 1];
    const uint4* in4 = (const uint4*)g_h16[1];
    float acc[8] = {};
    for (int base = b; base < e; base += 32) {
        int cnt = e - base;
        int sj = 0;
        unsigned wjp = 0;
        if (base + lane < e) {
            sj = g_srcc[base + lane];
            wjp = g_aw16[base + lane];
        }
        gather2_chunk(in4, cnt, h, lo, head1, sj, wjp, acc);
    }
    combine16(acc);
    float ts[8];
    feat_trans8(acc, lo, 2, scale, offset, pemb, ts);
    if (lane < 16) {
        store_half8(g_h16[2], gw * 16 + lo, acc);
        store_half8(g_hs16[1], gw * 16 + lo, ts);
    }
}

// ---------------- hop 3 + feat_trans + hop attention + residual + bias -------
__global__ __launch_bounds__(256) void hop3_final_kernel(
    const float* __restrict__ scale, const float* __restrict__ offset,
    const float* __restrict__ pemb,
    const float* __restrict__ attn_l, const float* __restrict__ attn_r,
    const float* __restrict__ bias,
    float* __restrict__ out)
{
    int gw = (blockIdx.x * blockDim.x + threadIdx.x) >> 5;
    int lane = threadIdx.x & 31;
    if (gw >= Nn) return;
    int h = lane >> 4, lo = lane & 15;
    bool head1 = (lo >= 8);
    int b = g_rp[gw], e = g_rp[gw + 1];
    const uint4* in4 = (const uint4*)g_h16[2];
    float acc[8] = {};
    for (int base = b; base < e; base += 32) {
        int cnt = e - base;
        int sj = 0;
        unsigned wjp = 0;
        if (base + lane < e) {
            sj = g_srcc[base + lane];
            wjp = g_aw16[base + lane];
        }
        gather2_chunk(in4, cnt, h, lo, head1, sj, wjp, acc);
    }
    combine16(acc);
    float s2[8];
    feat_trans8(acc, lo, 3, scale, offset, pemb, s2);

    // all lanes load via lo (upper half-warp duplicates lower; reductions in
    // 8-lane groups stay consistent)
    float s0[8], s1[8], h0[8];
    load_half8(g_hs16[0], gw * 16 + lo, s0);
    load_half8(g_hs16[1], gw * 16 + lo, s1);
    load_half8(g_hs16[2], gw * 16 + lo, h0);
    const float4* al4 = (const float4*)&attn_l[lo * 8];
    const float4* ar4 = (const float4*)&attn_r[lo * 8];
    float4 ala = al4[0], alb = al4[1];
    float4 ara = ar4[0], arb = ar4[1];
    float alv[8] = {ala.x, ala.y, ala.z, ala.w, alb.x, alb.y, alb.z, alb.w};
    float arv[8] = {ara.x, ara.y, ara.z, ara.w, arb.x, arb.y, arb.z, arb.w};

    float al = 0.f, w0 = 0.f, w1 = 0.f, w2 = 0.f;
    #pragma unroll
    for (int i = 0; i < 8; i++) {
        al += h0[i] * alv[i];
        w0 += s0[i] * arv[i];
        w1 += s1[i] * arv[i];
        w2 += s2[i] * arv[i];
    }
    #pragma unroll
    for (int o = 4; o; o >>= 1) {
        al += __shfl_xor_sync(0xffffffffu, al, o, 8);
        w0 += __shfl_xor_sync(0xffffffffu, w0, o, 8);
        w1 += __shfl_xor_sync(0xffffffffu, w1, o, 8);
        w2 += __shfl_xor_sync(0xffffffffu, w2, o, 8);
    }
    float l0 = leaky(w0 + al), l1 = leaky(w1 + al), l2 = leaky(w2 + al);
    float m = fmaxf(l0, fmaxf(l1, l2));
    float e0 = __expf(l0 - m), e1 = __expf(l1 - m), e2 = __expf(l2 - m);
    float inv = 1.f / (e0 + e1 + e2);
    e0 *= inv; e1 *= inv; e2 *= inv;

    if (lane < 16) {
        const float4* hd4 = (const float4*)&g_hdst[gw * HD + lo * 8];
        float4 hda = hd4[0], hdb = hd4[1];
        const float4* b4 = (const float4*)&bias[lo * 8];
        float4 ba = b4[0], bb = b4[1];
        float hdv[8] = {hda.x, hda.y, hda.z, hda.w, hdb.x, hdb.y, hdb.z, hdb.w};
        float bv[8]  = {ba.x, ba.y, ba.z, ba.w, bb.x, bb.y, bb.z, bb.w};
        float o8[8];
        #pragma unroll
        for (int i = 0; i < 8; i++)
            o8[i] = s0[i] * e0 + s1[i] * e1 + s2[i] * e2 + hdv[i] + bv[i];
        float4* out4 = (float4*)&out[gw * HD + lo * 8];
        out4[0] = make_float4(o8[0], o8[1], o8[2], o8[3]);
        out4[1] = make_float4(o8[4], o8[5], o8[6], o8[7]);
    }
}

// ---------------- launch ------------------------------------------------------
extern "C" void kernel_launch(void* const* d_in, const int* in_sizes, int n_in,
                              void* d_out, int out_size)
{
    const float* feat  = (const float*)d_in[0];
    const int*   src   = (const int*)d_in[1];
    const int*   dst   = (const int*)d_in[2];
    const float* Wsrc  = (const float*)d_in[3];
    const float* Wdst  = (const float*)d_in[4];
    const float* bdst  = (const float*)d_in[5];
    const float* Wasrc = (const float*)d_in[6];
    const float* Wadst = (const float*)d_in[7];
    const float* scale = (const float*)d_in[8];
    const float* offs  = (const float*)d_in[9];
    const float* pemb  = (const float*)d_in[10];
    const float* hal   = (const float*)d_in[11];
    const float* har   = (const float*)d_in[12];
    float* out = (float*)d_out;

    const int EG = (Ee + 255) / 256;
    const int NWG = (Nn * 32 + 255) / 256;

    wconv_kernel<<<(FIN * HD / 2 + 255) / 256, 256>>>(Wsrc, Wdst);
    convert_attn_kernel<<<NWG, 256>>>(feat, Wasrc, Wadst);
    gemm_tc_kernel<<<dim3((Nn + 127) / 128, 4), 256>>>();
    hist_kernel<<<(Ee / 4 + 255) / 256, 256>>>(dst);
    scan_kernel<<<1, 1024>>>();
    place_edge_kernel<<<EG, 256>>>(src, dst);
    ft0_kernel<<<NWG, 256>>>(scale, offs, pemb);
    hop1_kernel<<<NWG, 256>>>(scale, offs, pemb);
    hop2_kernel<<<NWG, 256>>>(scale, offs, pemb);
    hop3_final_kernel<<<NWG, 256>>>(scale, offs, pemb, hal, har, bdst, out);
}

// round 14
// speedup vs baseline: 1.0068x; 1.0068x over previous
#include <cuda_runtime.h>
#include <cuda_fp16.h>
#include <mma.h>

using namespace nvcuda;

#define Nn 50000
#define Ee 1600000
#define FIN 256
#define HD 128
#define NEG 0.2f
#define EPSf 1e-9f

// ---------------- scratch (static device globals) ----------------------------
__device__ float  g_hsrc[Nn * HD];        // fp32 h_src
__device__ float  g_hdst[Nn * HD];        // residual branch (bias added at end)
__device__ __half g_feat16[Nn * FIN];     // fp16 feat for TC GEMM
__device__ __half g_w16[2][FIN * HD];     // fp16 W_src / W_dst
__device__ __half g_h16[3][Nn * HD];      // fp16 gather sources
__device__ __half g_hs16[3][Nn * HD];     // fp16 transformed hops: [0]=hs1,[1]=hs2,[2]=h0
__device__ float  g_asrc[Nn * 2];
__device__ float  g_adst[Nn * 2];
__device__ float  g_acsr[Ee * 2];         // CSR: exp(logit) then (after hop1) weight
__device__ int    g_srcc[Ee];
__device__ int    g_cnt[Nn];
__device__ int    g_rp[Nn + 1];
__device__ int    g_cur[Nn];
__device__ float  g_sums[Nn * 2];         // src-direction softmax denominators

__device__ __forceinline__ float leaky(float x) { return x > 0.f ? x : NEG * x; }

// ---------------- W fp32 -> fp16 (tiny) --------------------------------------
__global__ void wconv_kernel(const float* __restrict__ Wsrc,
                             const float* __restrict__ Wdst)
{
    int i = blockIdx.x * blockDim.x + threadIdx.x;
    if (i < FIN * HD / 2) {
        float2 a = ((const float2*)Wsrc)[i];
        float2 b = ((const float2*)Wdst)[i];
        *(__half2*)&g_w16[0][i * 2] = __floats2half2_rn(a.x, a.y);
        *(__half2*)&g_w16[1][i * 2] = __floats2half2_rn(b.x, b.y);
    }
}

// ---------------- fused: feat fp32->fp16 + attention projections -------------
__global__ void convert_attn_kernel(const float* __restrict__ feat,
                                    const float* __restrict__ Wasrc,
                                    const float* __restrict__ Wadst)
{
    int gw = (blockIdx.x * blockDim.x + threadIdx.x) >> 5;
    int lane = threadIdx.x & 31;
    if (gw >= Nn) return;
    const float4* frow = (const float4*)&feat[gw * FIN];
    float4 x0 = frow[lane];
    float4 x1 = frow[lane + 32];
    uint2 r0, r1;
    *(__half2*)&r0.x = __floats2half2_rn(x0.x, x0.y);
    *(__half2*)&r0.y = __floats2half2_rn(x0.z, x0.w);
    *(__half2*)&r1.x = __floats2half2_rn(x1.x, x1.y);
    *(__half2*)&r1.y = __floats2half2_rn(x1.z, x1.w);
    ((uint2*)g_feat16)[gw * 64 + lane] = r0;
    ((uint2*)g_feat16)[gw * 64 + 32 + lane] = r1;

    int c0 = lane * 4, c1 = 128 + lane * 4;
    float s0 = 0.f, s1 = 0.f, d0 = 0.f, d1 = 0.f;
    #pragma unroll
    for (int j = 0; j < 4; j++) {
        float xa = (&x0.x)[j];
        float2 ws = ((const float2*)Wasrc)[c0 + j];
        float2 wd = ((const float2*)Wadst)[c0 + j];
        s0 += xa * ws.x; s1 += xa * ws.y;
        d0 += xa * wd.x; d1 += xa * wd.y;
        float xb = (&x1.x)[j];
        float2 ws1 = ((const float2*)Wasrc)[c1 + j];
        float2 wd1 = ((const float2*)Wadst)[c1 + j];
        s0 += xb * ws1.x; s1 += xb * ws1.y;
        d0 += xb * wd1.x; d1 += xb * wd1.y;
    }
    #pragma unroll
    for (int o = 16; o; o >>= 1) {
        s0 += __shfl_xor_sync(0xffffffffu, s0, o);
        s1 += __shfl_xor_sync(0xffffffffu, s1, o);
        d0 += __shfl_xor_sync(0xffffffffu, d0, o);
        d1 += __shfl_xor_sync(0xffffffffu, d1, o);
    }
    if (lane == 0) {
        ((float2*)g_asrc)[gw] = make_float2(s0, s1);
        ((float2*)g_adst)[gw] = make_float2(d0, d1);
    }
}

// ---------------- tensor-core GEMM: Out = feat16 @ W16 -----------------------
__global__ __launch_bounds__(256) void gemm_tc_kernel()
{
    __shared__ __half Bs[FIN * 64];
    int wsel = blockIdx.y & 1;
    int nhalf = blockIdx.y >> 1;
    const uint2* wsrc = (const uint2*)g_w16[wsel];
    uint2* bs = (uint2*)Bs;
    for (int i = threadIdx.x; i < FIN * 16; i += 256) {
        int r = i >> 4, c = i & 15;
        bs[r * 16 + c] = wsrc[r * 32 + nhalf * 16 + c];
    }
    __syncthreads();
    int wid = threadIdx.x >> 5;
    int row0 = blockIdx.x * 128 + wid * 16;
    if (row0 >= Nn) return;

    wmma::fragment<wmma::accumulator, 16, 16, 16, float> acc[4];
    #pragma unroll
    for (int n = 0; n < 4; n++) wmma::fill_fragment(acc[n], 0.f);
    const __half* arow = g_feat16 + row0 * FIN;
    #pragma unroll 4
    for (int kt = 0; kt < 16; kt++) {
        wmma::fragment<wmma::matrix_a, 16, 16, 16, __half, wmma::row_major> af;
        wmma::load_matrix_sync(af, arow + kt * 16, FIN);
        #pragma unroll
        for (int n = 0; n < 4; n++) {
            wmma::fragment<wmma::matrix_b, 16, 16, 16, __half, wmma::row_major> bf;
            wmma::load_matrix_sync(bf, Bs + kt * 16 * 64 + n * 16, 64);
            wmma::mma_sync(acc[n], af, bf, acc[n]);
        }
    }
    float* Out = wsel ? g_hdst : g_hsrc;
    #pragma unroll
    for (int n = 0; n < 4; n++)
        wmma::store_matrix_sync(Out + row0 * HD + nhalf * 64 + n * 16,
                                acc[n], HD, wmma::mem_row_major);
}

// ---------------- CSR build --------------------------------------------------
__global__ void hist_kernel(const int* __restrict__ dst) {
    int i = blockIdx.x * blockDim.x + threadIdx.x;   // 4 edges per thread
    int e0 = i * 4;
    if (e0 + 3 < Ee) {
        int4 d = ((const int4*)dst)[i];
        atomicAdd(&g_cnt[d.x], 1);
        atomicAdd(&g_cnt[d.y], 1);
        atomicAdd(&g_cnt[d.z], 1);
        atomicAdd(&g_cnt[d.w], 1);
    } else {
        for (int e = e0; e < Ee; e++) atomicAdd(&g_cnt[dst[e]], 1);
    }
}

// scan also re-zeroes cnt and sums for the NEXT call (deterministic per call:
// hist/place within one call see zeros from the previous call's scan, or
// static zero-init on the very first call).
__global__ __launch_bounds__(1024) void scan_kernel() {
    __shared__ int part[1024];
    const int CH = (Nn + 1023) / 1024;
    int t = threadIdx.x;
    int start = t * CH;
    int s = 0;
    for (int i = 0; i < CH; i++) {
        int idx = start + i;
        if (idx < Nn) s += g_cnt[idx];
    }
    part[t] = s;
    __syncthreads();
    for (int off = 1; off < 1024; off <<= 1) {
        int v = (t >= off) ? part[t - off] : 0;
        __syncthreads();
        part[t] += v;
        __syncthreads();
    }
    int base = (t == 0) ? 0 : part[t - 1];
    for (int i = 0; i < CH; i++) {
        int idx = start + i;
        if (idx < Nn) {
            int c = g_cnt[idx];
            g_rp[idx] = base;
            g_cur[idx] = base;
            base += c;
            g_cnt[idx] = 0;
            ((float2*)g_sums)[idx] = make_float2(0.f, 0.f);
        }
    }
    if (t == 1023) g_rp[Nn] = Ee;
}

// ---------------- place + edge logits/exp + src-sum atomics ------------------
__global__ void place_edge_kernel(const int* __restrict__ src, const int* __restrict__ dst) {
    int e = blockIdx.x * blockDim.x + threadIdx.x;
    if (e >= Ee) return;
    int s = src[e], d = dst[e];
    int pos = atomicAdd(&g_cur[d], 1);
    g_srcc[pos] = s;
    float2 as = ((const float2*)g_asrc)[s];
    float2 ad = ((const float2*)g_adst)[d];
    float e0 = __expf(leaky(as.x + ad.x));
    float e1 = __expf(leaky(as.y + ad.y));
    ((float2*)g_acsr)[pos] = make_float2(e0, e1);
    atomicAdd(&g_sums[s * 2], e0);     atomicAdd(&g_sums[s * 2 + 1], e1);
}

// ---------------- shared feat_trans epilogue helper --------------------------
__device__ __forceinline__ float4 feat_trans4(
    float4 acc, int lane, int k,
    const float* __restrict__ scale, const float* __restrict__ offset,
    const float* __restrict__ pemb)
{
    float s = acc.x + acc.y + acc.z + acc.w;
    float sq = acc.x * acc.x + acc.y * acc.y + acc.z * acc.z + acc.w * acc.w;
    #pragma unroll
    for (int o = 8; o; o >>= 1) {
        s  += __shfl_xor_sync(0xffffffffu, s,  o, 16);
        sq += __shfl_xor_sync(0xffffffffu, sq, o, 16);
    }
    float mean = s * (1.f / 64.f);
    float var = sq * (1.f / 64.f) - mean * mean + EPSf;
    float rs = rsqrtf(var);
    float4 sc = ((const float4*)scale)[k * 32 + lane];
    float4 of = ((const float4*)offset)[k * 32 + lane];
    float4 pe = ((const float4*)pemb)[k * 32 + lane];
    float4 y;
    y.x = (acc.x - mean) * sc.x * rs + of.x + pe.x;
    y.y = (acc.y - mean) * sc.y * rs + of.y + pe.y;
    y.z = (acc.z - mean) * sc.z * rs + of.z + pe.z;
    y.w = (acc.w - mean) * sc.w * rs + of.w + pe.w;
    return y;
}

__device__ __forceinline__ void store_half4(__half* __restrict__ out16,
                                            int idx4, float4 v)
{
    uint2 raw;
    *(__half2*)&raw.x = __floats2half2_rn(v.x, v.y);
    *(__half2*)&raw.y = __floats2half2_rn(v.z, v.w);
    ((uint2*)out16)[idx4] = raw;
}

__device__ __forceinline__ float4 load_half4(const __half* __restrict__ in16,
                                             int idx4)
{
    uint2 raw = ((const uint2*)in16)[idx4];
    float2 lo = __half22float2(*(const __half2*)&raw.x);
    float2 hi = __half22float2(*(const __half2*)&raw.y);
    return make_float4(lo.x, lo.y, hi.x, hi.y);
}

// ---------------- ft0: feat_trans(h_src,0) -> h0 (fp16), + fp16 h_src --------
__global__ void ft0_kernel(const float* __restrict__ scale,
                           const float* __restrict__ offset,
                           const float* __restrict__ pemb)
{
    int gw = (blockIdx.x * blockDim.x + threadIdx.x) >> 5;
    int lane = threadIdx.x & 31;
    if (gw >= Nn) return;
    float4 x = ((const float4*)g_hsrc)[gw * 32 + lane];
    store_half4(g_h16[0], gw * 32 + lane, x);
    store_half4(g_hs16[2], gw * 32 + lane,
                feat_trans4(x, lane, 0, scale, offset, pemb));
}

// ---------------- fp16 gather core with warp register caching ----------------
template<bool NORM>
__device__ __forceinline__ float4 gather_row(const __half* __restrict__ in16,
                                             int b, int e, int lane, int hh,
                                             float2 sd)
{
    const uint2* in = (const uint2*)in16;
    float4 acc = make_float4(0.f, 0.f, 0.f, 0.f);
    for (int base = b; base < e; base += 32) {
        int cnt = e - base;
        int sj = 0;
        float2 aj = make_float2(0.f, 0.f);
        if (base + lane < e) {
            sj = g_srcc[base + lane];
            aj = ((const float2*)g_acsr)[base + lane];
            if (NORM) {
                float2 ss = ((const float2*)g_sums)[sj];
                aj.x = sqrtf(fmaxf(aj.x / sd.x, EPSf) * fmaxf(aj.x / ss.x, EPSf));
                aj.y = sqrtf(fmaxf(aj.y / sd.y, EPSf) * fmaxf(aj.y / ss.y, EPSf));
                ((float2*)g_acsr)[base + lane] = aj;
            }
        }
        if (cnt >= 32) {
            #pragma unroll 8
            for (int j = 0; j < 32; j++) {
                int s = __shfl_sync(0xffffffffu, sj, j);
                float a0 = __shfl_sync(0xffffffffu, aj.x, j);
                float a1 = __shfl_sync(0xffffffffu, aj.y, j);
                float a = hh ? a1 : a0;
                uint2 raw = in[s * 32 + lane];
                float2 lo = __half22float2(*(const __half2*)&raw.x);
                float2 hi = __half22float2(*(const __half2*)&raw.y);
                acc.x += a * lo.x; acc.y += a * lo.y;
                acc.z += a * hi.x; acc.w += a * hi.y;
            }
        } else {
            for (int j = 0; j < cnt; j++) {
                int s = __shfl_sync(0xffffffffu, sj, j);
                float a0 = __shfl_sync(0xffffffffu, aj.x, j);
                float a1 = __shfl_sync(0xffffffffu, aj.y, j);
                float a = hh ? a1 : a0;
                uint2 raw = in[s * 32 + lane];
                float2 lo = __half22float2(*(const __half2*)&raw.x);
                float2 hi = __half22float2(*(const __half2*)&raw.y);
                acc.x += a * lo.x; acc.y += a * lo.y;
                acc.z += a * hi.x; acc.w += a * hi.y;
            }
        }
    }
    return acc;
}

// ---------------- hop 1: in-warp dst-sum + normalize + gather + feat_trans ---
__global__ __launch_bounds__(256) void hop1_kernel(
    const float* __restrict__ scale, const float* __restrict__ offset,
    const float* __restrict__ pemb)
{
    int gw = (blockIdx.x * blockDim.x + threadIdx.x) >> 5;
    int lane = threadIdx.x & 31;
    if (gw >= Nn) return;
    int hh = lane >> 4;
    int b = g_rp[gw], e = g_rp[gw + 1];

    // dst-direction denominator: coalesced pre-pass + full warp reduction
    float2 sd = make_float2(0.f, 0.f);
    for (int pos = b + lane; pos < e; pos += 32) {
        float2 ex = ((const float2*)g_acsr)[pos];
        sd.x += ex.x; sd.y += ex.y;
    }
    #pragma unroll
    for (int o = 16; o; o >>= 1) {
        sd.x += __shfl_xor_sync(0xffffffffu, sd.x, o);
        sd.y += __shfl_xor_sync(0xffffffffu, sd.y, o);
    }

    float4 acc = gather_row<true>(g_h16[0], b, e, lane, hh, sd);
    store_half4(g_h16[1], gw * 32 + lane, acc);
    store_half4(g_hs16[0], gw * 32 + lane,
                feat_trans4(acc, lane, 1, scale, offset, pemb));
}

// ---------------- hop 2: gather + feat_trans ---------------------------------
__global__ __launch_bounds__(256) void hop2_kernel(
    const float* __restrict__ scale, const float* __restrict__ offset,
    const float* __restrict__ pemb)
{
    int gw = (blockIdx.x * blockDim.x + threadIdx.x) >> 5;
    int lane = threadIdx.x & 31;
    if (gw >= Nn) return;
    int hh = lane >> 4;
    int b = g_rp[gw], e = g_rp[gw + 1];
    float4 acc = gather_row<false>(g_h16[1], b, e, lane, hh,
                                   make_float2(1.f, 1.f));
    store_half4(g_h16[2], gw * 32 + lane, acc);
    store_half4(g_hs16[1], gw * 32 + lane,
                feat_trans4(acc, lane, 2, scale, offset, pemb));
}

// ---------------- hop 3 + feat_trans + hop attention + residual + bias -------
__global__ __launch_bounds__(256) void hop3_final_kernel(
    const float* __restrict__ scale, const float* __restrict__ offset,
    const float* __restrict__ pemb,
    const float* __restrict__ attn_l, const float* __restrict__ attn_r,
    const float* __restrict__ bias,
    float* __restrict__ out)
{
    int gw = (blockIdx.x * blockDim.x + threadIdx.x) >> 5;
    int lane = threadIdx.x & 31;
    if (gw >= Nn) return;
    int hh = lane >> 4;
    int b = g_rp[gw], e = g_rp[gw + 1];
    float4 acc = gather_row<false>(g_h16[2], b, e, lane, hh,
                                   make_float2(1.f, 1.f));
    float4 s2 = feat_trans4(acc, lane, 3, scale, offset, pemb);

    float4 s0 = load_half4(g_hs16[0], gw * 32 + lane);
    float4 s1 = load_half4(g_hs16[1], gw * 32 + lane);
    float4 h0 = load_half4(g_hs16[2], gw * 32 + lane);
    float4 al4 = ((const float4*)attn_l)[lane];
    float4 ar4 = ((const float4*)attn_r)[lane];

    float al = h0.x * al4.x + h0.y * al4.y + h0.z * al4.z + h0.w * al4.w;
    float w0 = s0.x * ar4.x + s0.y * ar4.y + s0.z * ar4.z + s0.w * ar4.w;
    float w1 = s1.x * ar4.x + s1.y * ar4.y + s1.z * ar4.z + s1.w * ar4.w;
    float w2 = s2.x * ar4.x + s2.y * ar4.y + s2.z * ar4.z + s2.w * ar4.w;
    #pragma unroll
    for (int o = 8; o; o >>= 1) {
        al += __shfl_xor_sync(0xffffffffu, al, o, 16);
        w0 += __shfl_xor_sync(0xffffffffu, w0, o, 16);
        w1 += __shfl_xor_sync(0xffffffffu, w1, o, 16);
        w2 += __shfl_xor_sync(0xffffffffu, w2, o, 16);
    }
    float l0 = leaky(w0 + al), l1 = leaky(w1 + al), l2 = leaky(w2 + al);
    float m = fmaxf(l0, fmaxf(l1, l2));
    float e0 = __expf(l0 - m), e1 = __expf(l1 - m), e2 = __expf(l2 - m);
    float inv = 1.f / (e0 + e1 + e2);
    e0 *= inv; e1 *= inv; e2 *= inv;

    float4 hd = ((const float4*)g_hdst)[gw * 32 + lane];
    float4 b4 = ((const float4*)bias)[lane];
    float4 o4;
    o4.x = s0.x * e0 + s1.x * e1 + s2.x * e2 + hd.x + b4.x;
    o4.y = s0.y * e0 + s1.y * e1 + s2.y * e2 + hd.y + b4.y;
    o4.z = s0.z * e0 + s1.z * e1 + s2.z * e2 + hd.z + b4.z;
    o4.w = s0.w * e0 + s1.w * e1 + s2.w * e2 + hd.w + b4.w;
    ((float4*)out)[gw * 32 + lane] = o4;
}

// ---------------- launch ------------------------------------------------------
extern "C" void kernel_launch(void* const* d_in, const int* in_sizes, int n_in,
                              void* d_out, int out_size)
{
    const float* feat  = (const float*)d_in[0];
    const int*   src   = (const int*)d_in[1];
    const int*   dst   = (const int*)d_in[2];
    const float* Wsrc  = (const float*)d_in[3];
    const float* Wdst  = (const float*)d_in[4];
    const float* bdst  = (const float*)d_in[5];
    const float* Wasrc = (const float*)d_in[6];
    const float* Wadst = (const float*)d_in[7];
    const float* scale = (const float*)d_in[8];
    const float* offs  = (const float*)d_in[9];
    const float* pemb  = (const float*)d_in[10];
    const float* hal   = (const float*)d_in[11];
    const float* har   = (const float*)d_in[12];
    float* out = (float*)d_out;

    const int EG = (Ee + 255) / 256;
    const int NWG = (Nn * 32 + 255) / 256;

    wconv_kernel<<<(FIN * HD / 2 + 255) / 256, 256>>>(Wsrc, Wdst);
    convert_attn_kernel<<<NWG, 256>>>(feat, Wasrc, Wadst);
    gemm_tc_kernel<<<dim3((Nn + 127) / 128, 4), 256>>>();
    hist_kernel<<<(Ee / 4 + 255) / 256, 256>>>(dst);
    scan_kernel<<<1, 1024>>>();
    place_edge_kernel<<<EG, 256>>>(src, dst);
    ft0_kernel<<<NWG, 256>>>(scale, offs, pemb);
    hop1_kernel<<<NWG, 256>>>(scale, offs, pemb);
    hop2_kernel<<<NWG, 256>>>(scale, offs, pemb);
    hop3_final_kernel<<<NWG, 256>>>(scale, offs, pemb, hal, har, bdst, out);
}

// round 15
// speedup vs baseline: 1.2851x; 1.2764x over previous
#include <cuda_runtime.h>
#include <cuda_fp16.h>
#include <mma.h>

using namespace nvcuda;

#define Nn 50000
#define Ee 1600000
#define FIN 256
#define HD 128
#define NEG 0.2f
#define EPSf 1e-9f
#define NB 196          // ceil(Nn/256)

// ---------------- scratch (static device globals) ----------------------------
__device__ float  g_hsrc[Nn * HD];        // fp32 h_src
__device__ float  g_hdst[Nn * HD];        // residual branch (bias added at end)
__device__ __half g_feat16[Nn * FIN];     // fp16 feat for TC GEMM
__device__ __half g_w16[2][FIN * HD];     // fp16 W_src / W_dst
__device__ __half g_h16[3][Nn * HD];      // fp16 gather sources
__device__ __half g_hs16[3][Nn * HD];     // fp16 transformed hops: [0]=hs1,[1]=hs2,[2]=h0
__device__ float  g_asrc[Nn * 2];
__device__ float  g_adst[Nn * 2];
__device__ float  g_acsr[Ee * 2];         // CSR: exp(logit) then (after hop1) weight
__device__ int    g_srcc[Ee];
__device__ int    g_cnt[Nn];
__device__ int    g_rp[Nn + 1];
__device__ int    g_cur[Nn];
__device__ int    g_bsum[NB];
__device__ int    g_boff[NB];
__device__ float  g_sums[Nn * 2];         // src-direction softmax denominators

__device__ __forceinline__ float leaky(float x) { return x > 0.f ? x : NEG * x; }

// ---------------- W fp32 -> fp16 (tiny) --------------------------------------
__global__ void wconv_kernel(const float* __restrict__ Wsrc,
                             const float* __restrict__ Wdst)
{
    int i = blockIdx.x * blockDim.x + threadIdx.x;
    if (i < FIN * HD / 2) {
        float2 a = ((const float2*)Wsrc)[i];
        float2 b = ((const float2*)Wdst)[i];
        *(__half2*)&g_w16[0][i * 2] = __floats2half2_rn(a.x, a.y);
        *(__half2*)&g_w16[1][i * 2] = __floats2half2_rn(b.x, b.y);
    }
}

// ---------------- fused: feat fp32->fp16 + attention projections -------------
__global__ void convert_attn_kernel(const float* __restrict__ feat,
                                    const float* __restrict__ Wasrc,
                                    const float* __restrict__ Wadst)
{
    int gw = (blockIdx.x * blockDim.x + threadIdx.x) >> 5;
    int lane = threadIdx.x & 31;
    if (gw >= Nn) return;
    const float4* frow = (const float4*)&feat[gw * FIN];
    float4 x0 = frow[lane];
    float4 x1 = frow[lane + 32];
    uint2 r0, r1;
    *(__half2*)&r0.x = __floats2half2_rn(x0.x, x0.y);
    *(__half2*)&r0.y = __floats2half2_rn(x0.z, x0.w);
    *(__half2*)&r1.x = __floats2half2_rn(x1.x, x1.y);
    *(__half2*)&r1.y = __floats2half2_rn(x1.z, x1.w);
    ((uint2*)g_feat16)[gw * 64 + lane] = r0;
    ((uint2*)g_feat16)[gw * 64 + 32 + lane] = r1;

    int c0 = lane * 4, c1 = 128 + lane * 4;
    float s0 = 0.f, s1 = 0.f, d0 = 0.f, d1 = 0.f;
    #pragma unroll
    for (int j = 0; j < 4; j++) {
        float xa = (&x0.x)[j];
        float2 ws = ((const float2*)Wasrc)[c0 + j];
        float2 wd = ((const float2*)Wadst)[c0 + j];
        s0 += xa * ws.x; s1 += xa * ws.y;
        d0 += xa * wd.x; d1 += xa * wd.y;
        float xb = (&x1.x)[j];
        float2 ws1 = ((const float2*)Wasrc)[c1 + j];
        float2 wd1 = ((const float2*)Wadst)[c1 + j];
        s0 += xb * ws1.x; s1 += xb * ws1.y;
        d0 += xb * wd1.x; d1 += xb * wd1.y;
    }
    #pragma unroll
    for (int o = 16; o; o >>= 1) {
        s0 += __shfl_xor_sync(0xffffffffu, s0, o);
        s1 += __shfl_xor_sync(0xffffffffu, s1, o);
        d0 += __shfl_xor_sync(0xffffffffu, d0, o);
        d1 += __shfl_xor_sync(0xffffffffu, d1, o);
    }
    if (lane == 0) {
        ((float2*)g_asrc)[gw] = make_float2(s0, s1);
        ((float2*)g_adst)[gw] = make_float2(d0, d1);
    }
}

// ---------------- tensor-core GEMM: Out = feat16 @ W16 -----------------------
__global__ __launch_bounds__(256) void gemm_tc_kernel()
{
    __shared__ __half Bs[FIN * 64];
    int wsel = blockIdx.y & 1;
    int nhalf = blockIdx.y >> 1;
    const uint2* wsrc = (const uint2*)g_w16[wsel];
    uint2* bs = (uint2*)Bs;
    for (int i = threadIdx.x; i < FIN * 16; i += 256) {
        int r = i >> 4, c = i & 15;
        bs[r * 16 + c] = wsrc[r * 32 + nhalf * 16 + c];
    }
    __syncthreads();
    int wid = threadIdx.x >> 5;
    int row0 = blockIdx.x * 128 + wid * 16;
    if (row0 >= Nn) return;

    wmma::fragment<wmma::accumulator, 16, 16, 16, float> acc[4];
    #pragma unroll
    for (int n = 0; n < 4; n++) wmma::fill_fragment(acc[n], 0.f);
    const __half* arow = g_feat16 + row0 * FIN;
    #pragma unroll 4
    for (int kt = 0; kt < 16; kt++) {
        wmma::fragment<wmma::matrix_a, 16, 16, 16, __half, wmma::row_major> af;
        wmma::load_matrix_sync(af, arow + kt * 16, FIN);
        #pragma unroll
        for (int n = 0; n < 4; n++) {
            wmma::fragment<wmma::matrix_b, 16, 16, 16, __half, wmma::row_major> bf;
            wmma::load_matrix_sync(bf, Bs + kt * 16 * 64 + n * 16, 64);
            wmma::mma_sync(acc[n], af, bf, acc[n]);
        }
    }
    float* Out = wsel ? g_hdst : g_hsrc;
    #pragma unroll
    for (int n = 0; n < 4; n++)
        wmma::store_matrix_sync(Out + row0 * HD + nhalf * 64 + n * 16,
                                acc[n], HD, wmma::mem_row_major);
}

// ---------------- CSR build --------------------------------------------------
__global__ void hist_kernel(const int* __restrict__ dst) {
    int i = blockIdx.x * blockDim.x + threadIdx.x;   // 4 edges per thread
    int e0 = i * 4;
    if (e0 + 3 < Ee) {
        int4 d = ((const int4*)dst)[i];
        atomicAdd(&g_cnt[d.x], 1);
        atomicAdd(&g_cnt[d.y], 1);
        atomicAdd(&g_cnt[d.z], 1);
        atomicAdd(&g_cnt[d.w], 1);
    } else {
        for (int e = e0; e < Ee; e++) atomicAdd(&g_cnt[dst[e]], 1);
    }
}

// ---- parallel 3-phase exclusive scan of g_cnt -> g_rp / g_cur ---------------
// scanA: per-block (256-wide) exclusive scan; local prefix -> rp, total -> bsum
__global__ __launch_bounds__(256) void scanA_kernel() {
    __shared__ int sh[256];
    int t = threadIdx.x;
    int idx = blockIdx.x * 256 + t;
    int c = (idx < Nn) ? g_cnt[idx] : 0;
    sh[t] = c;
    __syncthreads();
    #pragma unroll
    for (int off = 1; off < 256; off <<= 1) {
        int v = (t >= off) ? sh[t - off] : 0;
        __syncthreads();
        sh[t] += v;
        __syncthreads();
    }
    if (idx < Nn) g_rp[idx] = sh[t] - c;        // local exclusive prefix
    if (t == 255) g_bsum[blockIdx.x] = sh[255]; // block total
}

// scanB: scan the 196 block totals (one tiny block)
__global__ __launch_bounds__(256) void scanB_kernel() {
    __shared__ int sh[256];
    int t = threadIdx.x;
    int c = (t < NB) ? g_bsum[t] : 0;
    sh[t] = c;
    __syncthreads();
    #pragma unroll
    for (int off = 1; off < 256; off <<= 1) {
        int v = (t >= off) ? sh[t - off] : 0;
        __syncthreads();
        sh[t] += v;
        __syncthreads();
    }
    if (t < NB) g_boff[t] = sh[t] - c;          // exclusive block offset
    if (t == 0) g_rp[Nn] = Ee;
}

// scanC: apply block offsets; init cur; zero cnt & sums for next call
__global__ __launch_bounds__(256) void scanC_kernel() {
    int idx = blockIdx.x * 256 + threadIdx.x;
    if (idx < Nn) {
        int r = g_rp[idx] + g_boff[blockIdx.x];
        g_rp[idx] = r;
        g_cur[idx] = r;
        g_cnt[idx] = 0;
        ((float2*)g_sums)[idx] = make_float2(0.f, 0.f);
    }
}

// ---------------- place + edge logits/exp + src-sum atomics ------------------
__global__ void place_edge_kernel(const int* __restrict__ src, const int* __restrict__ dst) {
    int e = blockIdx.x * blockDim.x + threadIdx.x;
    if (e >= Ee) return;
    int s = src[e], d = dst[e];
    int pos = atomicAdd(&g_cur[d], 1);
    g_srcc[pos] = s;
    float2 as = ((const float2*)g_asrc)[s];
    float2 ad = ((const float2*)g_adst)[d];
    float e0 = __expf(leaky(as.x + ad.x));
    float e1 = __expf(leaky(as.y + ad.y));
    ((float2*)g_acsr)[pos] = make_float2(e0, e1);
    atomicAdd(&g_sums[s * 2], e0);     atomicAdd(&g_sums[s * 2 + 1], e1);
}

// ---------------- shared feat_trans epilogue helper --------------------------
__device__ __forceinline__ float4 feat_trans4(
    float4 acc, int lane, int k,
    const float* __restrict__ scale, const float* __restrict__ offset,
    const float* __restrict__ pemb)
{
    float s = acc.x + acc.y + acc.z + acc.w;
    float sq = acc.x * acc.x + acc.y * acc.y + acc.z * acc.z + acc.w * acc.w;
    #pragma unroll
    for (int o = 8; o; o >>= 1) {
        s  += __shfl_xor_sync(0xffffffffu, s,  o, 16);
        sq += __shfl_xor_sync(0xffffffffu, sq, o, 16);
    }
    float mean = s * (1.f / 64.f);
    float var = sq * (1.f / 64.f) - mean * mean + EPSf;
    float rs = rsqrtf(var);
    float4 sc = ((const float4*)scale)[k * 32 + lane];
    float4 of = ((const float4*)offset)[k * 32 + lane];
    float4 pe = ((const float4*)pemb)[k * 32 + lane];
    float4 y;
    y.x = (acc.x - mean) * sc.x * rs + of.x + pe.x;
    y.y = (acc.y - mean) * sc.y * rs + of.y + pe.y;
    y.z = (acc.z - mean) * sc.z * rs + of.z + pe.z;
    y.w = (acc.w - mean) * sc.w * rs + of.w + pe.w;
    return y;
}

__device__ __forceinline__ void store_half4(__half* __restrict__ out16,
                                            int idx4, float4 v)
{
    uint2 raw;
    *(__half2*)&raw.x = __floats2half2_rn(v.x, v.y);
    *(__half2*)&raw.y = __floats2half2_rn(v.z, v.w);
    ((uint2*)out16)[idx4] = raw;
}

__device__ __forceinline__ float4 load_half4(const __half* __restrict__ in16,
                                             int idx4)
{
    uint2 raw = ((const uint2*)in16)[idx4];
    float2 lo = __half22float2(*(const __half2*)&raw.x);
    float2 hi = __half22float2(*(const __half2*)&raw.y);
    return make_float4(lo.x, lo.y, hi.x, hi.y);
}

// ---------------- ft0: feat_trans(h_src,0) -> h0 (fp16), + fp16 h_src --------
__global__ void ft0_kernel(const float* __restrict__ scale,
                           const float* __restrict__ offset,
                           const float* __restrict__ pemb)
{
    int gw = (blockIdx.x * blockDim.x + threadIdx.x) >> 5;
    int lane = threadIdx.x & 31;
    if (gw >= Nn) return;
    float4 x = ((const float4*)g_hsrc)[gw * 32 + lane];
    store_half4(g_h16[0], gw * 32 + lane, x);
    store_half4(g_hs16[2], gw * 32 + lane,
                feat_trans4(x, lane, 0, scale, offset, pemb));
}

// ---------------- fp16 gather core with warp register caching ----------------
template<bool NORM>
__device__ __forceinline__ float4 gather_row(const __half* __restrict__ in16,
                                             int b, int e, int lane, int hh,
                                             float2 sd)
{
    const uint2* in = (const uint2*)in16;
    float4 acc = make_float4(0.f, 0.f, 0.f, 0.f);
    for (int base = b; base < e; base += 32) {
        int cnt = e - base;
        int sj = 0;
        float2 aj = make_float2(0.f, 0.f);
        if (base + lane < e) {
            sj = g_srcc[base + lane];
            aj = ((const float2*)g_acsr)[base + lane];
            if (NORM) {
                float2 ss = ((const float2*)g_sums)[sj];
                aj.x = sqrtf(fmaxf(aj.x / sd.x, EPSf) * fmaxf(aj.x / ss.x, EPSf));
                aj.y = sqrtf(fmaxf(aj.y / sd.y, EPSf) * fmaxf(aj.y / ss.y, EPSf));
                ((float2*)g_acsr)[base + lane] = aj;
            }
        }
        if (cnt >= 32) {
            #pragma unroll 8
            for (int j = 0; j < 32; j++) {
                int s = __shfl_sync(0xffffffffu, sj, j);
                float a0 = __shfl_sync(0xffffffffu, aj.x, j);
                float a1 = __shfl_sync(0xffffffffu, aj.y, j);
                float a = hh ? a1 : a0;
                uint2 raw = in[s * 32 + lane];
                float2 lo = __half22float2(*(const __half2*)&raw.x);
                float2 hi = __half22float2(*(const __half2*)&raw.y);
                acc.x += a * lo.x; acc.y += a * lo.y;
                acc.z += a * hi.x; acc.w += a * hi.y;
            }
        } else {
            for (int j = 0; j < cnt; j++) {
                int s = __shfl_sync(0xffffffffu, sj, j);
                float a0 = __shfl_sync(0xffffffffu, aj.x, j);
                float a1 = __shfl_sync(0xffffffffu, aj.y, j);
                float a = hh ? a1 : a0;
                uint2 raw = in[s * 32 + lane];
                float2 lo = __half22float2(*(const __half2*)&raw.x);
                float2 hi = __half22float2(*(const __half2*)&raw.y);
                acc.x += a * lo.x; acc.y += a * lo.y;
                acc.z += a * hi.x; acc.w += a * hi.y;
            }
        }
    }
    return acc;
}

// ---------------- hop 1: in-warp dst-sum + normalize + gather + feat_trans ---
__global__ __launch_bounds__(256) void hop1_kernel(
    const float* __restrict__ scale, const float* __restrict__ offset,
    const float* __restrict__ pemb)
{
    int gw = (blockIdx.x * blockDim.x + threadIdx.x) >> 5;
    int lane = threadIdx.x & 31;
    if (gw >= Nn) return;
    int hh = lane >> 4;
    int b = g_rp[gw], e = g_rp[gw + 1];

    // dst-direction denominator: coalesced pre-pass + full warp reduction
    float2 sd = make_float2(0.f, 0.f);
    for (int pos = b + lane; pos < e; pos += 32) {
        float2 ex = ((const float2*)g_acsr)[pos];
        sd.x += ex.x; sd.y += ex.y;
    }
    #pragma unroll
    for (int o = 16; o; o >>= 1) {
        sd.x += __shfl_xor_sync(0xffffffffu, sd.x, o);
        sd.y += __shfl_xor_sync(0xffffffffu, sd.y, o);
    }

    float4 acc = gather_row<true>(g_h16[0], b, e, lane, hh, sd);
    store_half4(g_h16[1], gw * 32 + lane, acc);
    store_half4(g_hs16[0], gw * 32 + lane,
                feat_trans4(acc, lane, 1, scale, offset, pemb));
}

// ---------------- hop 2: gather + feat_trans ---------------------------------
__global__ __launch_bounds__(256) void hop2_kernel(
    const float* __restrict__ scale, const float* __restrict__ offset,
    const float* __restrict__ pemb)
{
    int gw = (blockIdx.x * blockDim.x + threadIdx.x) >> 5;
    int lane = threadIdx.x & 31;
    if (gw >= Nn) return;
    int hh = lane >> 4;
    int b = g_rp[gw], e = g_rp[gw + 1];
    float4 acc = gather_row<false>(g_h16[1], b, e, lane, hh,
                                   make_float2(1.f, 1.f));
    store_half4(g_h16[2], gw * 32 + lane, acc);
    store_half4(g_hs16[1], gw * 32 + lane,
                feat_trans4(acc, lane, 2, scale, offset, pemb));
}

// ---------------- hop 3 + feat_trans + hop attention + residual + bias -------
__global__ __launch_bounds__(256) void hop3_final_kernel(
    const float* __restrict__ scale, const float* __restrict__ offset,
    const float* __restrict__ pemb,
    const float* __restrict__ attn_l, const float* __restrict__ attn_r,
    const float* __restrict__ bias,
    float* __restrict__ out)
{
    int gw = (blockIdx.x * blockDim.x + threadIdx.x) >> 5;
    int lane = threadIdx.x & 31;
    if (gw >= Nn) return;
    int hh = lane >> 4;
    int b = g_rp[gw], e = g_rp[gw + 1];
    float4 acc = gather_row<false>(g_h16[2], b, e, lane, hh,
                                   make_float2(1.f, 1.f));
    float4 s2 = feat_trans4(acc, lane, 3, scale, offset, pemb);

    float4 s0 = load_half4(g_hs16[0], gw * 32 + lane);
    float4 s1 = load_half4(g_hs16[1], gw * 32 + lane);
    float4 h0 = load_half4(g_hs16[2], gw * 32 + lane);
    float4 al4 = ((const float4*)attn_l)[lane];
    float4 ar4 = ((const float4*)attn_r)[lane];

    float al = h0.x * al4.x + h0.y * al4.y + h0.z * al4.z + h0.w * al4.w;
    float w0 = s0.x * ar4.x + s0.y * ar4.y + s0.z * ar4.z + s0.w * ar4.w;
    float w1 = s1.x * ar4.x + s1.y * ar4.y + s1.z * ar4.z + s1.w * ar4.w;
    float w2 = s2.x * ar4.x + s2.y * ar4.y + s2.z * ar4.z + s2.w * ar4.w;
    #pragma unroll
    for (int o = 8; o; o >>= 1) {
        al += __shfl_xor_sync(0xffffffffu, al, o, 16);
        w0 += __shfl_xor_sync(0xffffffffu, w0, o, 16);
        w1 += __shfl_xor_sync(0xffffffffu, w1, o, 16);
        w2 += __shfl_xor_sync(0xffffffffu, w2, o, 16);
    }
    float l0 = leaky(w0 + al), l1 = leaky(w1 + al), l2 = leaky(w2 + al);
    float m = fmaxf(l0, fmaxf(l1, l2));
    float e0 = __expf(l0 - m), e1 = __expf(l1 - m), e2 = __expf(l2 - m);
    float inv = 1.f / (e0 + e1 + e2);
    e0 *= inv; e1 *= inv; e2 *= inv;

    float4 hd = ((const float4*)g_hdst)[gw * 32 + lane];
    float4 b4 = ((const float4*)bias)[lane];
    float4 o4;
    o4.x = s0.x * e0 + s1.x * e1 + s2.x * e2 + hd.x + b4.x;
    o4.y = s0.y * e0 + s1.y * e1 + s2.y * e2 + hd.y + b4.y;
    o4.z = s0.z * e0 + s1.z * e1 + s2.z * e2 + hd.z + b4.z;
    o4.w = s0.w * e0 + s1.w * e1 + s2.w * e2 + hd.w + b4.w;
    ((float4*)out)[gw * 32 + lane] = o4;
}

// ---------------- launch ------------------------------------------------------
extern "C" void kernel_launch(void* const* d_in, const int* in_sizes, int n_in,
                              void* d_out, int out_size)
{
    const float* feat  = (const float*)d_in[0];
    const int*   src   = (const int*)d_in[1];
    const int*   dst   = (const int*)d_in[2];
    const float* Wsrc  = (const float*)d_in[3];
    const float* Wdst  = (const float*)d_in[4];
    const float* bdst  = (const float*)d_in[5];
    const float* Wasrc = (const float*)d_in[6];
    const float* Wadst = (const float*)d_in[7];
    const float* scale = (const float*)d_in[8];
    const float* offs  = (const float*)d_in[9];
    const float* pemb  = (const float*)d_in[10];
    const float* hal   = (const float*)d_in[11];
    const float* har   = (const float*)d_in[12];
    float* out = (float*)d_out;

    const int EG = (Ee + 255) / 256;
    const int NWG = (Nn * 32 + 255) / 256;

    convert_attn_kernel<<<NWG, 256>>>(feat, Wasrc, Wadst);
    wconv_kernel<<<(FIN * HD / 2 + 255) / 256, 256>>>(Wsrc, Wdst);
    gemm_tc_kernel<<<dim3((Nn + 127) / 128, 4), 256>>>();

    hist_kernel<<<(Ee / 4 + 255) / 256, 256>>>(dst);
    scanA_kernel<<<NB, 256>>>();
    scanB_kernel<<<1, 256>>>();
    scanC_kernel<<<NB, 256>>>();
    place_edge_kernel<<<EG, 256>>>(src, dst);

    ft0_kernel<<<NWG, 256>>>(scale, offs, pemb);
    hop1_kernel<<<NWG, 256>>>(scale, offs, pemb);
    hop2_kernel<<<NWG, 256>>>(scale, offs, pemb);
    hop3_final_kernel<<<NWG, 256>>>(scale, offs, pemb, hal, har, bdst, out);
}

// round 16
// speedup vs baseline: 1.3144x; 1.0228x over previous
#include <cuda_runtime.h>
#include <cuda_fp16.h>
#include <mma.h>

using namespace nvcuda;

#define Nn 50000
#define Ee 1600000
#define FIN 256
#define HD 128
#define NEG 0.2f
#define EPSf 1e-9f
#define NB 196            // ceil(Nn/256)
#define NWG 6250          // node-warp grid (Nn*32/256)
#define WCONVB 64         // wconv blocks
#define HISTB 1563        // hist blocks (Ee/4/256)
#define GEMMX 391         // ceil(Nn/128)

// ---------------- scratch (static device globals) ----------------------------
__device__ float  g_hsrc[Nn * HD];
__device__ float  g_hdst[Nn * HD];
__device__ __half g_feat16[Nn * FIN];
__device__ __half g_w16[2][FIN * HD];
__device__ __half g_h16[3][Nn * HD];
__device__ __half g_hs16[3][Nn * HD];
__device__ float  g_asrc[Nn * 2];
__device__ float  g_adst[Nn * 2];
__device__ float  g_acsr[Ee * 2];
__device__ int    g_srcc[Ee];
__device__ int    g_cnt[Nn];
__device__ int    g_rp[Nn + 1];
__device__ int    g_cur[Nn];
__device__ int    g_bsum[NB];
__device__ int    g_boff[NB];
__device__ float  g_sums[Nn * 2];

__device__ __forceinline__ float leaky(float x) { return x > 0.f ? x : NEG * x; }

// ---------------- device bodies ----------------------------------------------
__device__ void wconv_body(int bid, const float* __restrict__ Wsrc,
                           const float* __restrict__ Wdst)
{
    int i = bid * 256 + threadIdx.x;
    if (i < FIN * HD / 2) {
        float2 a = ((const float2*)Wsrc)[i];
        float2 b = ((const float2*)Wdst)[i];
        *(__half2*)&g_w16[0][i * 2] = __floats2half2_rn(a.x, a.y);
        *(__half2*)&g_w16[1][i * 2] = __floats2half2_rn(b.x, b.y);
    }
}

__device__ void convert_attn_body(int bid, const float* __restrict__ feat,
                                  const float* __restrict__ Wasrc,
                                  const float* __restrict__ Wadst)
{
    int gw = (bid * 256 + threadIdx.x) >> 5;
    int lane = threadIdx.x & 31;
    if (gw >= Nn) return;
    const float4* frow = (const float4*)&feat[gw * FIN];
    float4 x0 = frow[lane];
    float4 x1 = frow[lane + 32];
    uint2 r0, r1;
    *(__half2*)&r0.x = __floats2half2_rn(x0.x, x0.y);
    *(__half2*)&r0.y = __floats2half2_rn(x0.z, x0.w);
    *(__half2*)&r1.x = __floats2half2_rn(x1.x, x1.y);
    *(__half2*)&r1.y = __floats2half2_rn(x1.z, x1.w);
    ((uint2*)g_feat16)[gw * 64 + lane] = r0;
    ((uint2*)g_feat16)[gw * 64 + 32 + lane] = r1;

    int c0 = lane * 4, c1 = 128 + lane * 4;
    float s0 = 0.f, s1 = 0.f, d0 = 0.f, d1 = 0.f;
    #pragma unroll
    for (int j = 0; j < 4; j++) {
        float xa = (&x0.x)[j];
        float2 ws = ((const float2*)Wasrc)[c0 + j];
        float2 wd = ((const float2*)Wadst)[c0 + j];
        s0 += xa * ws.x; s1 += xa * ws.y;
        d0 += xa * wd.x; d1 += xa * wd.y;
        float xb = (&x1.x)[j];
        float2 ws1 = ((const float2*)Wasrc)[c1 + j];
        float2 wd1 = ((const float2*)Wadst)[c1 + j];
        s0 += xb * ws1.x; s1 += xb * ws1.y;
        d0 += xb * wd1.x; d1 += xb * wd1.y;
    }
    #pragma unroll
    for (int o = 16; o; o >>= 1) {
        s0 += __shfl_xor_sync(0xffffffffu, s0, o);
        s1 += __shfl_xor_sync(0xffffffffu, s1, o);
        d0 += __shfl_xor_sync(0xffffffffu, d0, o);
        d1 += __shfl_xor_sync(0xffffffffu, d1, o);
    }
    if (lane == 0) {
        ((float2*)g_asrc)[gw] = make_float2(s0, s1);
        ((float2*)g_adst)[gw] = make_float2(d0, d1);
    }
}

__device__ void hist_body(int bid, const int* __restrict__ dst)
{
    int i = bid * 256 + threadIdx.x;
    int e0 = i * 4;
    if (e0 + 3 < Ee) {
        int4 d = ((const int4*)dst)[i];
        atomicAdd(&g_cnt[d.x], 1);
        atomicAdd(&g_cnt[d.y], 1);
        atomicAdd(&g_cnt[d.z], 1);
        atomicAdd(&g_cnt[d.w], 1);
    } else {
        for (int e = e0; e < Ee; e++) atomicAdd(&g_cnt[dst[e]], 1);
    }
}

// ---------------- K1: convert_attn | wconv | hist ----------------------------
__global__ __launch_bounds__(256) void k1_kernel(
    const float* __restrict__ feat,
    const float* __restrict__ Wasrc, const float* __restrict__ Wadst,
    const float* __restrict__ Wsrc,  const float* __restrict__ Wdst,
    const int* __restrict__ dst)
{
    int b = blockIdx.x;
    if (b < NWG)                 convert_attn_body(b, feat, Wasrc, Wadst);
    else if (b < NWG + WCONVB)   wconv_body(b - NWG, Wsrc, Wdst);
    else                         hist_body(b - NWG - WCONVB, dst);
}

// ---------------- gemm / scanA bodies ----------------------------------------
__device__ void gemm_body(int gx, int gy, __half* Bs)
{
    int wsel = gy & 1;
    int nhalf = gy >> 1;
    const uint2* wsrc = (const uint2*)g_w16[wsel];
    uint2* bs = (uint2*)Bs;
    for (int i = threadIdx.x; i < FIN * 16; i += 256) {
        int r = i >> 4, c = i & 15;
        bs[r * 16 + c] = wsrc[r * 32 + nhalf * 16 + c];
    }
    __syncthreads();
    int wid = threadIdx.x >> 5;
    int row0 = gx * 128 + wid * 16;
    if (row0 >= Nn) return;

    wmma::fragment<wmma::accumulator, 16, 16, 16, float> acc[4];
    #pragma unroll
    for (int n = 0; n < 4; n++) wmma::fill_fragment(acc[n], 0.f);
    const __half* arow = g_feat16 + row0 * FIN;
    #pragma unroll 4
    for (int kt = 0; kt < 16; kt++) {
        wmma::fragment<wmma::matrix_a, 16, 16, 16, __half, wmma::row_major> af;
        wmma::load_matrix_sync(af, arow + kt * 16, FIN);
        #pragma unroll
        for (int n = 0; n < 4; n++) {
            wmma::fragment<wmma::matrix_b, 16, 16, 16, __half, wmma::row_major> bf;
            wmma::load_matrix_sync(bf, Bs + kt * 16 * 64 + n * 16, 64);
            wmma::mma_sync(acc[n], af, bf, acc[n]);
        }
    }
    float* Out = wsel ? g_hdst : g_hsrc;
    #pragma unroll
    for (int n = 0; n < 4; n++)
        wmma::store_matrix_sync(Out + row0 * HD + nhalf * 64 + n * 16,
                                acc[n], HD, wmma::mem_row_major);
}

__device__ void scanA_body(int bid, int* sh)
{
    int t = threadIdx.x;
    int idx = bid * 256 + t;
    int c = (idx < Nn) ? g_cnt[idx] : 0;
    sh[t] = c;
    __syncthreads();
    #pragma unroll
    for (int off = 1; off < 256; off <<= 1) {
        int v = (t >= off) ? sh[t - off] : 0;
        __syncthreads();
        sh[t] += v;
        __syncthreads();
    }
    if (idx < Nn) g_rp[idx] = sh[t] - c;
    if (t == 255) g_bsum[bid] = sh[255];
}

// ---------------- K2: gemm_tc | scanA ----------------------------------------
__global__ __launch_bounds__(256) void k2_kernel()
{
    __shared__ __half Bs[FIN * 64];     // 32 KB (scanA reuses first 1 KB as int)
    int b = blockIdx.x;
    if (b < GEMMX * 4) {
        gemm_body(b % GEMMX, b / GEMMX, Bs);
    } else {
        scanA_body(b - GEMMX * 4, (int*)Bs);
    }
}

// ---------------- K3: scanB (tiny) -------------------------------------------
__global__ __launch_bounds__(256) void scanB_kernel() {
    __shared__ int sh[256];
    int t = threadIdx.x;
    int c = (t < NB) ? g_bsum[t] : 0;
    sh[t] = c;
    __syncthreads();
    #pragma unroll
    for (int off = 1; off < 256; off <<= 1) {
        int v = (t >= off) ? sh[t - off] : 0;
        __syncthreads();
        sh[t] += v;
        __syncthreads();
    }
    if (t < NB) g_boff[t] = sh[t] - c;
    if (t == 0) g_rp[Nn] = Ee;
}

// ---------------- feat_trans / half helpers ----------------------------------
__device__ __forceinline__ float4 feat_trans4(
    float4 acc, int lane, int k,
    const float* __restrict__ scale, const float* __restrict__ offset,
    const float* __restrict__ pemb)
{
    float s = acc.x + acc.y + acc.z + acc.w;
    float sq = acc.x * acc.x + acc.y * acc.y + acc.z * acc.z + acc.w * acc.w;
    #pragma unroll
    for (int o = 8; o; o >>= 1) {
        s  += __shfl_xor_sync(0xffffffffu, s,  o, 16);
        sq += __shfl_xor_sync(0xffffffffu, sq, o, 16);
    }
    float mean = s * (1.f / 64.f);
    float var = sq * (1.f / 64.f) - mean * mean + EPSf;
    float rs = rsqrtf(var);
    float4 sc = ((const float4*)scale)[k * 32 + lane];
    float4 of = ((const float4*)offset)[k * 32 + lane];
    float4 pe = ((const float4*)pemb)[k * 32 + lane];
    float4 y;
    y.x = (acc.x - mean) * sc.x * rs + of.x + pe.x;
    y.y = (acc.y - mean) * sc.y * rs + of.y + pe.y;
    y.z = (acc.z - mean) * sc.z * rs + of.z + pe.z;
    y.w = (acc.w - mean) * sc.w * rs + of.w + pe.w;
    return y;
}

__device__ __forceinline__ void store_half4(__half* __restrict__ out16,
                                            int idx4, float4 v)
{
    uint2 raw;
    *(__half2*)&raw.x = __floats2half2_rn(v.x, v.y);
    *(__half2*)&raw.y = __floats2half2_rn(v.z, v.w);
    ((uint2*)out16)[idx4] = raw;
}

__device__ __forceinline__ float4 load_half4(const __half* __restrict__ in16,
                                             int idx4)
{
    uint2 raw = ((const uint2*)in16)[idx4];
    float2 lo = __half22float2(*(const __half2*)&raw.x);
    float2 hi = __half22float2(*(const __half2*)&raw.y);
    return make_float4(lo.x, lo.y, hi.x, hi.y);
}

// ---------------- ft0 / scanC bodies -----------------------------------------
__device__ void ft0_body(int bid, const float* __restrict__ scale,
                         const float* __restrict__ offset,
                         const float* __restrict__ pemb)
{
    int gw = (bid * 256 + threadIdx.x) >> 5;
    int lane = threadIdx.x & 31;
    if (gw >= Nn) return;
    float4 x = ((const float4*)g_hsrc)[gw * 32 + lane];
    store_half4(g_h16[0], gw * 32 + lane, x);
    store_half4(g_hs16[2], gw * 32 + lane,
                feat_trans4(x, lane, 0, scale, offset, pemb));
}

__device__ void scanC_body(int bid)
{
    int idx = bid * 256 + threadIdx.x;
    if (idx < Nn) {
        int r = g_rp[idx] + g_boff[bid];
        g_rp[idx] = r;
        g_cur[idx] = r;
        g_cnt[idx] = 0;
        ((float2*)g_sums)[idx] = make_float2(0.f, 0.f);
    }
}

// ---------------- K4: ft0 | scanC --------------------------------------------
__global__ __launch_bounds__(256) void k4_kernel(
    const float* __restrict__ scale, const float* __restrict__ offset,
    const float* __restrict__ pemb)
{
    int b = blockIdx.x;
    if (b < NWG) ft0_body(b, scale, offset, pemb);
    else         scanC_body(b - NWG);
}

// ---------------- place + edge logits/exp + src-sum atomics ------------------
__global__ void place_edge_kernel(const int* __restrict__ src, const int* __restrict__ dst) {
    int e = blockIdx.x * blockDim.x + threadIdx.x;
    if (e >= Ee) return;
    int s = src[e], d = dst[e];
    int pos = atomicAdd(&g_cur[d], 1);
    g_srcc[pos] = s;
    float2 as = ((const float2*)g_asrc)[s];
    float2 ad = ((const float2*)g_adst)[d];
    float e0 = __expf(leaky(as.x + ad.x));
    float e1 = __expf(leaky(as.y + ad.y));
    ((float2*)g_acsr)[pos] = make_float2(e0, e1);
    atomicAdd(&g_sums[s * 2], e0);     atomicAdd(&g_sums[s * 2 + 1], e1);
}

// ---------------- fp16 gather core with warp register caching ----------------
template<bool NORM>
__device__ __forceinline__ float4 gather_row(const __half* __restrict__ in16,
                                             int b, int e, int lane, int hh,
                                             float2 sd)
{
    const uint2* in = (const uint2*)in16;
    float4 acc = make_float4(0.f, 0.f, 0.f, 0.f);
    for (int base = b; base < e; base += 32) {
        int cnt = e - base;
        int sj = 0;
        float2 aj = make_float2(0.f, 0.f);
        if (base + lane < e) {
            sj = g_srcc[base + lane];
            aj = ((const float2*)g_acsr)[base + lane];
            if (NORM) {
                float2 ss = ((const float2*)g_sums)[sj];
                aj.x = sqrtf(fmaxf(aj.x / sd.x, EPSf) * fmaxf(aj.x / ss.x, EPSf));
                aj.y = sqrtf(fmaxf(aj.y / sd.y, EPSf) * fmaxf(aj.y / ss.y, EPSf));
                ((float2*)g_acsr)[base + lane] = aj;
            }
        }
        if (cnt >= 32) {
            #pragma unroll 8
            for (int j = 0; j < 32; j++) {
                int s = __shfl_sync(0xffffffffu, sj, j);
                float a0 = __shfl_sync(0xffffffffu, aj.x, j);
                float a1 = __shfl_sync(0xffffffffu, aj.y, j);
                float a = hh ? a1 : a0;
                uint2 raw = in[s * 32 + lane];
                float2 lo = __half22float2(*(const __half2*)&raw.x);
                float2 hi = __half22float2(*(const __half2*)&raw.y);
                acc.x += a * lo.x; acc.y += a * lo.y;
                acc.z += a * hi.x; acc.w += a * hi.y;
            }
        } else {
            for (int j = 0; j < cnt; j++) {
                int s = __shfl_sync(0xffffffffu, sj, j);
                float a0 = __shfl_sync(0xffffffffu, aj.x, j);
                float a1 = __shfl_sync(0xffffffffu, aj.y, j);
                float a = hh ? a1 : a0;
                uint2 raw = in[s * 32 + lane];
                float2 lo = __half22float2(*(const __half2*)&raw.x);
                float2 hi = __half22float2(*(const __half2*)&raw.y);
                acc.x += a * lo.x; acc.y += a * lo.y;
                acc.z += a * hi.x; acc.w += a * hi.y;
            }
        }
    }
    return acc;
}

// ---------------- hop 1 ------------------------------------------------------
__global__ __launch_bounds__(256) void hop1_kernel(
    const float* __restrict__ scale, const float* __restrict__ offset,
    const float* __restrict__ pemb)
{
    int gw = (blockIdx.x * blockDim.x + threadIdx.x) >> 5;
    int lane = threadIdx.x & 31;
    if (gw >= Nn) return;
    int hh = lane >> 4;
    int b = g_rp[gw], e = g_rp[gw + 1];

    float2 sd = make_float2(0.f, 0.f);
    for (int pos = b + lane; pos < e; pos += 32) {
        float2 ex = ((const float2*)g_acsr)[pos];
        sd.x += ex.x; sd.y += ex.y;
    }
    #pragma unroll
    for (int o = 16; o; o >>= 1) {
        sd.x += __shfl_xor_sync(0xffffffffu, sd.x, o);
        sd.y += __shfl_xor_sync(0xffffffffu, sd.y, o);
    }

    float4 acc = gather_row<true>(g_h16[0], b, e, lane, hh, sd);
    store_half4(g_h16[1], gw * 32 + lane, acc);
    store_half4(g_hs16[0], gw * 32 + lane,
                feat_trans4(acc, lane, 1, scale, offset, pemb));
}

// ---------------- hop 2 ------------------------------------------------------
__global__ __launch_bounds__(256) void hop2_kernel(
    const float* __restrict__ scale, const float* __restrict__ offset,
    const float* __restrict__ pemb)
{
    int gw = (blockIdx.x * blockDim.x + threadIdx.x) >> 5;
    int lane = threadIdx.x & 31;
    if (gw >= Nn) return;
    int hh = lane >> 4;
    int b = g_rp[gw], e = g_rp[gw + 1];
    float4 acc = gather_row<false>(g_h16[1], b, e, lane, hh,
                                   make_float2(1.f, 1.f));
    store_half4(g_h16[2], gw * 32 + lane, acc);
    store_half4(g_hs16[1], gw * 32 + lane,
                feat_trans4(acc, lane, 2, scale, offset, pemb));
}

// ---------------- hop 3 + hop attention + residual + bias --------------------
__global__ __launch_bounds__(256) void hop3_final_kernel(
    const float* __restrict__ scale, const float* __restrict__ offset,
    const float* __restrict__ pemb,
    const float* __restrict__ attn_l, const float* __restrict__ attn_r,
    const float* __restrict__ bias,
    float* __restrict__ out)
{
    int gw = (blockIdx.x * blockDim.x + threadIdx.x) >> 5;
    int lane = threadIdx.x & 31;
    if (gw >= Nn) return;
    int hh = lane >> 4;
    int b = g_rp[gw], e = g_rp[gw + 1];
    float4 acc = gather_row<false>(g_h16[2], b, e, lane, hh,
                                   make_float2(1.f, 1.f));
    float4 s2 = feat_trans4(acc, lane, 3, scale, offset, pemb);

    float4 s0 = load_half4(g_hs16[0], gw * 32 + lane);
    float4 s1 = load_half4(g_hs16[1], gw * 32 + lane);
    float4 h0 = load_half4(g_hs16[2], gw * 32 + lane);
    float4 al4 = ((const float4*)attn_l)[lane];
    float4 ar4 = ((const float4*)attn_r)[lane];

    float al = h0.x * al4.x + h0.y * al4.y + h0.z * al4.z + h0.w * al4.w;
    float w0 = s0.x * ar4.x + s0.y * ar4.y + s0.z * ar4.z + s0.w * ar4.w;
    float w1 = s1.x * ar4.x + s1.y * ar4.y + s1.z * ar4.z + s1.w * ar4.w;
    float w2 = s2.x * ar4.x + s2.y * ar4.y + s2.z * ar4.z + s2.w * ar4.w;
    #pragma unroll
    for (int o = 8; o; o >>= 1) {
        al += __shfl_xor_sync(0xffffffffu, al, o, 16);
        w0 += __shfl_xor_sync(0xffffffffu, w0, o, 16);
        w1 += __shfl_xor_sync(0xffffffffu, w1, o, 16);
        w2 += __shfl_xor_sync(0xffffffffu, w2, o, 16);
    }
    float l0 = leaky(w0 + al), l1 = leaky(w1 + al), l2 = leaky(w2 + al);
    float m = fmaxf(l0, fmaxf(l1, l2));
    float e0 = __expf(l0 - m), e1 = __expf(l1 - m), e2 = __expf(l2 - m);
    float inv = 1.f / (e0 + e1 + e2);
    e0 *= inv; e1 *= inv; e2 *= inv;

    float4 hd = ((const float4*)g_hdst)[gw * 32 + lane];
    float4 b4 = ((const float4*)bias)[lane];
    float4 o4;
    o4.x = s0.x * e0 + s1.x * e1 + s2.x * e2 + hd.x + b4.x;
    o4.y = s0.y * e0 + s1.y * e1 + s2.y * e2 + hd.y + b4.y;
    o4.z = s0.z * e0 + s1.z * e1 + s2.z * e2 + hd.z + b4.z;
    o4.w = s0.w * e0 + s1.w * e1 + s2.w * e2 + hd.w + b4.w;
    ((float4*)out)[gw * 32 + lane] = o4;
}

// ---------------- launch ------------------------------------------------------
extern "C" void kernel_launch(void* const* d_in, const int* in_sizes, int n_in,
                              void* d_out, int out_size)
{
    const float* feat  = (const float*)d_in[0];
    const int*   src   = (const int*)d_in[1];
    const int*   dst   = (const int*)d_in[2];
    const float* Wsrc  = (const float*)d_in[3];
    const float* Wdst  = (const float*)d_in[4];
    const float* bdst  = (const float*)d_in[5];
    const float* Wasrc = (const float*)d_in[6];
    const float* Wadst = (const float*)d_in[7];
    const float* scale = (const float*)d_in[8];
    const float* offs  = (const float*)d_in[9];
    const float* pemb  = (const float*)d_in[10];
    const float* hal   = (const float*)d_in[11];
    const float* har   = (const float*)d_in[12];
    float* out = (float*)d_out;

    const int EG = (Ee + 255) / 256;

    // K1: convert_attn | wconv | hist  (independent)
    k1_kernel<<<NWG + WCONVB + HISTB, 256>>>(feat, Wasrc, Wadst, Wsrc, Wdst, dst);
    // K2: gemm_tc | scanA
    k2_kernel<<<GEMMX * 4 + NB, 256>>>();
    // K3: scanB
    scanB_kernel<<<1, 256>>>();
    // K4: ft0 | scanC
    k4_kernel<<<NWG + NB, 256>>>(scale, offs, pemb);
    // place (needs scanC + asrc/adst)
    place_edge_kernel<<<EG, 256>>>(src, dst);
    // hops
    hop1_kernel<<<NWG, 256>>>(scale, offs, pemb);
    hop2_kernel<<<NWG, 256>>>(scale, offs, pemb);
    hop3_final_kernel<<<NWG, 256>>>(scale, offs, pemb, hal, har, bdst, out);
}

// round 17
// speedup vs baseline: 1.3222x; 1.0059x over previous
#include <cuda_runtime.h>
#include <cuda_fp16.h>
#include <mma.h>

using namespace nvcuda;

#define Nn 50000
#define Ee 1600000
#define FIN 256
#define HD 128
#define NEG 0.2f
#define EPSf 1e-9f
#define NB 196            // ceil(Nn/256)
#define NWG 6250          // node-warp grid (Nn*32/256)
#define WCONVB 64         // wconv blocks
#define HISTB 1563        // hist blocks (Ee/4/256)
#define GEMMX 391         // ceil(Nn/128)
#define EG 6250           // edge grid (Ee/256)

// ---------------- scratch (static device globals) ----------------------------
__device__ float  g_hsrc[Nn * HD];
__device__ float  g_hdst[Nn * HD];
__device__ __half g_feat16[Nn * FIN];
__device__ __half g_w16[2][FIN * HD];
__device__ __half g_h16[3][Nn * HD];
__device__ __half g_hs16[3][Nn * HD];
__device__ float  g_asrc[Nn * 2];
__device__ float  g_adst[Nn * 2];
__device__ float  g_acsr[Ee * 2];
__device__ int    g_srcc[Ee];
__device__ int    g_cnt[Nn];
__device__ int    g_rp[Nn + 1];
__device__ int    g_cur[Nn];
__device__ int    g_bsum[NB];
__device__ float  g_sums[Nn * 2];

__device__ __forceinline__ float leaky(float x) { return x > 0.f ? x : NEG * x; }

// ---------------- device bodies ----------------------------------------------
__device__ void wconv_body(int bid, const float* __restrict__ Wsrc,
                           const float* __restrict__ Wdst)
{
    int i = bid * 256 + threadIdx.x;
    if (i < FIN * HD / 2) {
        float2 a = ((const float2*)Wsrc)[i];
        float2 b = ((const float2*)Wdst)[i];
        *(__half2*)&g_w16[0][i * 2] = __floats2half2_rn(a.x, a.y);
        *(__half2*)&g_w16[1][i * 2] = __floats2half2_rn(b.x, b.y);
    }
}

__device__ void convert_attn_body(int bid, const float* __restrict__ feat,
                                  const float* __restrict__ Wasrc,
                                  const float* __restrict__ Wadst)
{
    int gw = (bid * 256 + threadIdx.x) >> 5;
    int lane = threadIdx.x & 31;
    if (gw >= Nn) return;
    const float4* frow = (const float4*)&feat[gw * FIN];
    float4 x0 = frow[lane];
    float4 x1 = frow[lane + 32];
    uint2 r0, r1;
    *(__half2*)&r0.x = __floats2half2_rn(x0.x, x0.y);
    *(__half2*)&r0.y = __floats2half2_rn(x0.z, x0.w);
    *(__half2*)&r1.x = __floats2half2_rn(x1.x, x1.y);
    *(__half2*)&r1.y = __floats2half2_rn(x1.z, x1.w);
    ((uint2*)g_feat16)[gw * 64 + lane] = r0;
    ((uint2*)g_feat16)[gw * 64 + 32 + lane] = r1;

    int c0 = lane * 4, c1 = 128 + lane * 4;
    float s0 = 0.f, s1 = 0.f, d0 = 0.f, d1 = 0.f;
    #pragma unroll
    for (int j = 0; j < 4; j++) {
        float xa = (&x0.x)[j];
        float2 ws = ((const float2*)Wasrc)[c0 + j];
        float2 wd = ((const float2*)Wadst)[c0 + j];
        s0 += xa * ws.x; s1 += xa * ws.y;
        d0 += xa * wd.x; d1 += xa * wd.y;
        float xb = (&x1.x)[j];
        float2 ws1 = ((const float2*)Wasrc)[c1 + j];
        float2 wd1 = ((const float2*)Wadst)[c1 + j];
        s0 += xb * ws1.x; s1 += xb * ws1.y;
        d0 += xb * wd1.x; d1 += xb * wd1.y;
    }
    #pragma unroll
    for (int o = 16; o; o >>= 1) {
        s0 += __shfl_xor_sync(0xffffffffu, s0, o);
        s1 += __shfl_xor_sync(0xffffffffu, s1, o);
        d0 += __shfl_xor_sync(0xffffffffu, d0, o);
        d1 += __shfl_xor_sync(0xffffffffu, d1, o);
    }
    if (lane == 0) {
        ((float2*)g_asrc)[gw] = make_float2(s0, s1);
        ((float2*)g_adst)[gw] = make_float2(d0, d1);
    }
}

__device__ void hist_body(int bid, const int* __restrict__ dst)
{
    int i = bid * 256 + threadIdx.x;
    int e0 = i * 4;
    if (e0 + 3 < Ee) {
        int4 d = ((const int4*)dst)[i];
        atomicAdd(&g_cnt[d.x], 1);
        atomicAdd(&g_cnt[d.y], 1);
        atomicAdd(&g_cnt[d.z], 1);
        atomicAdd(&g_cnt[d.w], 1);
    } else {
        for (int e = e0; e < Ee; e++) atomicAdd(&g_cnt[dst[e]], 1);
    }
}

// ---------------- K1: convert_attn | wconv | hist ----------------------------
__global__ __launch_bounds__(256) void k1_kernel(
    const float* __restrict__ feat,
    const float* __restrict__ Wasrc, const float* __restrict__ Wadst,
    const float* __restrict__ Wsrc,  const float* __restrict__ Wdst,
    const int* __restrict__ dst)
{
    int b = blockIdx.x;
    if (b < NWG)                 convert_attn_body(b, feat, Wasrc, Wadst);
    else if (b < NWG + WCONVB)   wconv_body(b - NWG, Wsrc, Wdst);
    else                         hist_body(b - NWG - WCONVB, dst);
}

// ---------------- gemm / scanA bodies ----------------------------------------
__device__ void gemm_body(int gx, int gy, __half* Bs)
{
    int wsel = gy & 1;
    int nhalf = gy >> 1;
    const uint2* wsrc = (const uint2*)g_w16[wsel];
    uint2* bs = (uint2*)Bs;
    for (int i = threadIdx.x; i < FIN * 16; i += 256) {
        int r = i >> 4, c = i & 15;
        bs[r * 16 + c] = wsrc[r * 32 + nhalf * 16 + c];
    }
    __syncthreads();
    int wid = threadIdx.x >> 5;
    int row0 = gx * 128 + wid * 16;
    if (row0 >= Nn) return;

    wmma::fragment<wmma::accumulator, 16, 16, 16, float> acc[4];
    #pragma unroll
    for (int n = 0; n < 4; n++) wmma::fill_fragment(acc[n], 0.f);
    const __half* arow = g_feat16 + row0 * FIN;
    #pragma unroll 4
    for (int kt = 0; kt < 16; kt++) {
        wmma::fragment<wmma::matrix_a, 16, 16, 16, __half, wmma::row_major> af;
        wmma::load_matrix_sync(af, arow + kt * 16, FIN);
        #pragma unroll
        for (int n = 0; n < 4; n++) {
            wmma::fragment<wmma::matrix_b, 16, 16, 16, __half, wmma::row_major> bf;
            wmma::load_matrix_sync(bf, Bs + kt * 16 * 64 + n * 16, 64);
            wmma::mma_sync(acc[n], af, bf, acc[n]);
        }
    }
    float* Out = wsel ? g_hdst : g_hsrc;
    #pragma unroll
    for (int n = 0; n < 4; n++)
        wmma::store_matrix_sync(Out + row0 * HD + nhalf * 64 + n * 16,
                                acc[n], HD, wmma::mem_row_major);
}

__device__ void scanA_body(int bid, int* sh)
{
    int t = threadIdx.x;
    int idx = bid * 256 + t;
    int c = (idx < Nn) ? g_cnt[idx] : 0;
    sh[t] = c;
    __syncthreads();
    #pragma unroll
    for (int off = 1; off < 256; off <<= 1) {
        int v = (t >= off) ? sh[t - off] : 0;
        __syncthreads();
        sh[t] += v;
        __syncthreads();
    }
    if (idx < Nn) g_rp[idx] = sh[t] - c;
    if (t == 255) g_bsum[bid] = sh[255];
}

// ---------------- K2: gemm_tc | scanA ----------------------------------------
__global__ __launch_bounds__(256) void k2_kernel()
{
    __shared__ __half Bs[FIN * 64];     // 32 KB (scanA reuses first 1 KB as int)
    int b = blockIdx.x;
    if (b < GEMMX * 4) {
        gemm_body(b % GEMMX, b / GEMMX, Bs);
    } else {
        scanA_body(b - GEMMX * 4, (int*)Bs);
    }
}

// ---------------- scanBC: every block scans the 196 block sums, applies own --
__global__ __launch_bounds__(256) void scanBC_kernel() {
    __shared__ int sh[256];
    int t = threadIdx.x;
    int own = (t < NB) ? g_bsum[t] : 0;
    sh[t] = own;
    __syncthreads();
    #pragma unroll
    for (int off = 1; off < 256; off <<= 1) {
        int v = (t >= off) ? sh[t - off] : 0;
        __syncthreads();
        sh[t] += v;
        __syncthreads();
    }
    __shared__ int boff_sh;
    if (t == (int)blockIdx.x)
        boff_sh = sh[t] - own;                      // exclusive offset for this block
    __syncthreads();
    int boff = boff_sh;
    int idx = blockIdx.x * 256 + t;
    if (idx < Nn) {
        int r = g_rp[idx] + boff;
        g_rp[idx] = r;
        g_cur[idx] = r;
        g_cnt[idx] = 0;
        ((float2*)g_sums)[idx] = make_float2(0.f, 0.f);
    }
    if (blockIdx.x == 0 && t == 0) g_rp[Nn] = Ee;
}

// ---------------- feat_trans / half helpers ----------------------------------
__device__ __forceinline__ float4 feat_trans4(
    float4 acc, int lane, int k,
    const float* __restrict__ scale, const float* __restrict__ offset,
    const float* __restrict__ pemb)
{
    float s = acc.x + acc.y + acc.z + acc.w;
    float sq = acc.x * acc.x + acc.y * acc.y + acc.z * acc.z + acc.w * acc.w;
    #pragma unroll
    for (int o = 8; o; o >>= 1) {
        s  += __shfl_xor_sync(0xffffffffu, s,  o, 16);
        sq += __shfl_xor_sync(0xffffffffu, sq, o, 16);
    }
    float mean = s * (1.f / 64.f);
    float var = sq * (1.f / 64.f) - mean * mean + EPSf;
    float rs = rsqrtf(var);
    float4 sc = ((const float4*)scale)[k * 32 + lane];
    float4 of = ((const float4*)offset)[k * 32 + lane];
    float4 pe = ((const float4*)pemb)[k * 32 + lane];
    float4 y;
    y.x = (acc.x - mean) * sc.x * rs + of.x + pe.x;
    y.y = (acc.y - mean) * sc.y * rs + of.y + pe.y;
    y.z = (acc.z - mean) * sc.z * rs + of.z + pe.z;
    y.w = (acc.w - mean) * sc.w * rs + of.w + pe.w;
    return y;
}

__device__ __forceinline__ void store_half4(__half* __restrict__ out16,
                                            int idx4, float4 v)
{
    uint2 raw;
    *(__half2*)&raw.x = __floats2half2_rn(v.x, v.y);
    *(__half2*)&raw.y = __floats2half2_rn(v.z, v.w);
    ((uint2*)out16)[idx4] = raw;
}

__device__ __forceinline__ float4 load_half4(const __half* __restrict__ in16,
                                             int idx4)
{
    uint2 raw = ((const uint2*)in16)[idx4];
    float2 lo = __half22float2(*(const __half2*)&raw.x);
    float2 hi = __half22float2(*(const __half2*)&raw.y);
    return make_float4(lo.x, lo.y, hi.x, hi.y);
}

// ---------------- ft0 / place bodies -----------------------------------------
__device__ void ft0_body(int bid, const float* __restrict__ scale,
                         const float* __restrict__ offset,
                         const float* __restrict__ pemb)
{
    int gw = (bid * 256 + threadIdx.x) >> 5;
    int lane = threadIdx.x & 31;
    if (gw >= Nn) return;
    float4 x = ((const float4*)g_hsrc)[gw * 32 + lane];
    store_half4(g_h16[0], gw * 32 + lane, x);
    store_half4(g_hs16[2], gw * 32 + lane,
                feat_trans4(x, lane, 0, scale, offset, pemb));
}

__device__ void place_body(int bid, const int* __restrict__ src,
                           const int* __restrict__ dst)
{
    int e = bid * 256 + threadIdx.x;
    if (e >= Ee) return;
    int s = src[e], d = dst[e];
    int pos = atomicAdd(&g_cur[d], 1);
    g_srcc[pos] = s;
    float2 as = ((const float2*)g_asrc)[s];
    float2 ad = ((const float2*)g_adst)[d];
    float e0 = __expf(leaky(as.x + ad.x));
    float e1 = __expf(leaky(as.y + ad.y));
    ((float2*)g_acsr)[pos] = make_float2(e0, e1);
    atomicAdd(&g_sums[s * 2], e0);     atomicAdd(&g_sums[s * 2 + 1], e1);
}

// ---------------- K4: place_edge | ft0 ---------------------------------------
__global__ __launch_bounds__(256) void k4_kernel(
    const int* __restrict__ src, const int* __restrict__ dst,
    const float* __restrict__ scale, const float* __restrict__ offset,
    const float* __restrict__ pemb)
{
    int b = blockIdx.x;
    if (b < EG) place_body(b, src, dst);
    else        ft0_body(b - EG, scale, offset, pemb);
}

// ---------------- fp16 gather core with warp register caching ----------------
template<bool NORM>
__device__ __forceinline__ float4 gather_row(const __half* __restrict__ in16,
                                             int b, int e, int lane, int hh,
                                             float2 sd)
{
    const uint2* in = (const uint2*)in16;
    float4 acc = make_float4(0.f, 0.f, 0.f, 0.f);
    for (int base = b; base < e; base += 32) {
        int cnt = e - base;
        int sj = 0;
        float2 aj = make_float2(0.f, 0.f);
        if (base + lane < e) {
            sj = g_srcc[base + lane];
            aj = ((const float2*)g_acsr)[base + lane];
            if (NORM) {
                float2 ss = ((const float2*)g_sums)[sj];
                aj.x = sqrtf(fmaxf(aj.x / sd.x, EPSf) * fmaxf(aj.x / ss.x, EPSf));
                aj.y = sqrtf(fmaxf(aj.y / sd.y, EPSf) * fmaxf(aj.y / ss.y, EPSf));
                ((float2*)g_acsr)[base + lane] = aj;
            }
        }
        if (cnt >= 32) {
            #pragma unroll 8
            for (int j = 0; j < 32; j++) {
                int s = __shfl_sync(0xffffffffu, sj, j);
                float a0 = __shfl_sync(0xffffffffu, aj.x, j);
                float a1 = __shfl_sync(0xffffffffu, aj.y, j);
                float a = hh ? a1 : a0;
                uint2 raw = in[s * 32 + lane];
                float2 lo = __half22float2(*(const __half2*)&raw.x);
                float2 hi = __half22float2(*(const __half2*)&raw.y);
                acc.x += a * lo.x; acc.y += a * lo.y;
                acc.z += a * hi.x; acc.w += a * hi.y;
            }
        } else {
            for (int j = 0; j < cnt; j++) {
                int s = __shfl_sync(0xffffffffu, sj, j);
                float a0 = __shfl_sync(0xffffffffu, aj.x, j);
                float a1 = __shfl_sync(0xffffffffu, aj.y, j);
                float a = hh ? a1 : a0;
                uint2 raw = in[s * 32 + lane];
                float2 lo = __half22float2(*(const __half2*)&raw.x);
                float2 hi = __half22float2(*(const __half2*)&raw.y);
                acc.x += a * lo.x; acc.y += a * lo.y;
                acc.z += a * hi.x; acc.w += a * hi.y;
            }
        }
    }
    return acc;
}

// ---------------- hop 1 ------------------------------------------------------
__global__ __launch_bounds__(256) void hop1_kernel(
    const float* __restrict__ scale, const float* __restrict__ offset,
    const float* __restrict__ pemb)
{
    int gw = (blockIdx.x * blockDim.x + threadIdx.x) >> 5;
    int lane = threadIdx.x & 31;
    if (gw >= Nn) return;
    int hh = lane >> 4;
    int b = g_rp[gw], e = g_rp[gw + 1];

    float2 sd = make_float2(0.f, 0.f);
    for (int pos = b + lane; pos < e; pos += 32) {
        float2 ex = ((const float2*)g_acsr)[pos];
        sd.x += ex.x; sd.y += ex.y;
    }
    #pragma unroll
    for (int o = 16; o; o >>= 1) {
        sd.x += __shfl_xor_sync(0xffffffffu, sd.x, o);
        sd.y += __shfl_xor_sync(0xffffffffu, sd.y, o);
    }

    float4 acc = gather_row<true>(g_h16[0], b, e, lane, hh, sd);
    store_half4(g_h16[1], gw * 32 + lane, acc);
    store_half4(g_hs16[0], gw * 32 + lane,
                feat_trans4(acc, lane, 1, scale, offset, pemb));
}

// ---------------- hop 2 ------------------------------------------------------
__global__ __launch_bounds__(256) void hop2_kernel(
    const float* __restrict__ scale, const float* __restrict__ offset,
    const float* __restrict__ pemb)
{
    int gw = (blockIdx.x * blockDim.x + threadIdx.x) >> 5;
    int lane = threadIdx.x & 31;
    if (gw >= Nn) return;
    int hh = lane >> 4;
    int b = g_rp[gw], e = g_rp[gw + 1];
    float4 acc = gather_row<false>(g_h16[1], b, e, lane, hh,
                                   make_float2(1.f, 1.f));
    store_half4(g_h16[2], gw * 32 + lane, acc);
    store_half4(g_hs16[1], gw * 32 + lane,
                feat_trans4(acc, lane, 2, scale, offset, pemb));
}

// ---------------- hop 3 + hop attention + residual + bias --------------------
__global__ __launch_bounds__(256) void hop3_final_kernel(
    const float* __restrict__ scale, const float* __restrict__ offset,
    const float* __restrict__ pemb,
    const float* __restrict__ attn_l, const float* __restrict__ attn_r,
    const float* __restrict__ bias,
    float* __restrict__ out)
{
    int gw = (blockIdx.x * blockDim.x + threadIdx.x) >> 5;
    int lane = threadIdx.x & 31;
    if (gw >= Nn) return;
    int hh = lane >> 4;
    int b = g_rp[gw], e = g_rp[gw + 1];
    float4 acc = gather_row<false>(g_h16[2], b, e, lane, hh,
                                   make_float2(1.f, 1.f));
    float4 s2 = feat_trans4(acc, lane, 3, scale, offset, pemb);

    float4 s0 = load_half4(g_hs16[0], gw * 32 + lane);
    float4 s1 = load_half4(g_hs16[1], gw * 32 + lane);
    float4 h0 = load_half4(g_hs16[2], gw * 32 + lane);
    float4 al4 = ((const float4*)attn_l)[lane];
    float4 ar4 = ((const float4*)attn_r)[lane];

    float al = h0.x * al4.x + h0.y * al4.y + h0.z * al4.z + h0.w * al4.w;
    float w0 = s0.x * ar4.x + s0.y * ar4.y + s0.z * ar4.z + s0.w * ar4.w;
    float w1 = s1.x * ar4.x + s1.y * ar4.y + s1.z * ar4.z + s1.w * ar4.w;
    float w2 = s2.x * ar4.x + s2.y * ar4.y + s2.z * ar4.z + s2.w * ar4.w;
    #pragma unroll
    for (int o = 8; o; o >>= 1) {
        al += __shfl_xor_sync(0xffffffffu, al, o, 16);
        w0 += __shfl_xor_sync(0xffffffffu, w0, o, 16);
        w1 += __shfl_xor_sync(0xffffffffu, w1, o, 16);
        w2 += __shfl_xor_sync(0xffffffffu, w2, o, 16);
    }
    float l0 = leaky(w0 + al), l1 = leaky(w1 + al), l2 = leaky(w2 + al);
    float m = fmaxf(l0, fmaxf(l1, l2));
    float e0 = __expf(l0 - m), e1 = __expf(l1 - m), e2 = __expf(l2 - m);
    float inv = 1.f / (e0 + e1 + e2);
    e0 *= inv; e1 *= inv; e2 *= inv;

    float4 hd = ((const float4*)g_hdst)[gw * 32 + lane];
    float4 b4 = ((const float4*)bias)[lane];
    float4 o4;
    o4.x = s0.x * e0 + s1.x * e1 + s2.x * e2 + hd.x + b4.x;
    o4.y = s0.y * e0 + s1.y * e1 + s2.y * e2 + hd.y + b4.y;
    o4.z = s0.z * e0 + s1.z * e1 + s2.z * e2 + hd.z + b4.z;
    o4.w = s0.w * e0 + s1.w * e1 + s2.w * e2 + hd.w + b4.w;
    ((float4*)out)[gw * 32 + lane] = o4;
}

// ---------------- launch ------------------------------------------------------
extern "C" void kernel_launch(void* const* d_in, const int* in_sizes, int n_in,
                              void* d_out, int out_size)
{
    const float* feat  = (const float*)d_in[0];
    const int*   src   = (const int*)d_in[1];
    const int*   dst   = (const int*)d_in[2];
    const float* Wsrc  = (const float*)d_in[3];
    const float* Wdst  = (const float*)d_in[4];
    const float* bdst  = (const float*)d_in[5];
    const float* Wasrc = (const float*)d_in[6];
    const float* Wadst = (const float*)d_in[7];
    const float* scale = (const float*)d_in[8];
    const float* offs  = (const float*)d_in[9];
    const float* pemb  = (const float*)d_in[10];
    const float* hal   = (const float*)d_in[11];
    const float* har   = (const float*)d_in[12];
    float* out = (float*)d_out;

    // K1: convert_attn | wconv | hist
    k1_kernel<<<NWG + WCONVB + HISTB, 256>>>(feat, Wasrc, Wadst, Wsrc, Wdst, dst);
    // K2: gemm_tc | scanA
    k2_kernel<<<GEMMX * 4 + NB, 256>>>();
    // scanBC: block-sum scan + apply + init cur + zero cnt/sums
    scanBC_kernel<<<NB, 256>>>();
    // K4: place_edge | ft0
    k4_kernel<<<EG + NWG, 256>>>(src, dst, scale, offs, pemb);
    // hops
    hop1_kernel<<<NWG, 256>>>(scale, offs, pemb);
    hop2_kernel<<<NWG, 256>>>(scale, offs, pemb);
    hop3_final_kernel<<<NWG, 256>>>(scale, offs, pemb, hal, har, bdst, out);
}